// round 1
// baseline (speedup 1.0000x reference)
#include <cuda_runtime.h>
#include <math.h>

#define TOK 8192
#define DIM 1024
#define NE  16

// ---------------- device scratch (static, allocation-free) ----------------
__device__ float g_wsum[DIM * DIM];          // folded shared-expert weight, 4 MB
__device__ int   g_ecount[NE];
__device__ int   g_eoff[NE];
__device__ float g_pi[NE];
__device__ int   g_cnt[NE];
__device__ int   g_etok[NE * TOK];           // per-expert gathered token ids
__device__ float g_ewt[NE * TOK];            // per-expert per-row combine weight
__device__ int   g_tk_e[TOK * 2];            // per-token chosen experts
__device__ int   g_tk_pos[TOK * 2];          // per-token position in expert list
__device__ float g_eout[TOK * 2 * DIM];      // expert GEMM outputs (weighted), 64 MB

// ---------------- reset per-launch state ----------------
__global__ void k_reset() {
    int i = threadIdx.x;
    if (i < NE) { g_ecount[i] = 0; g_pi[i] = 0.f; g_cnt[i] = 0; }
}

// ---------------- fold shared_w: Wsum[h,d] = sw[h,d] + sw[h+D,d] ----------------
__global__ void k_wsum(const float* __restrict__ sw) {
    int i = blockIdx.x * 256 + threadIdx.x;              // over DIM*DIM/4 float4
    const float4* s4 = (const float4*)sw;
    float4 a = s4[i];
    float4 b = s4[i + (DIM * DIM) / 4];
    float4 c = make_float4(a.x + b.x, a.y + b.y, a.z + b.z, a.w + b.w);
    ((float4*)g_wsum)[i] = c;
}

// ---------------- router: logits, top-2 softmax weights, pi/counts ----------------
__global__ void __launch_bounds__(256) k_router(const float* __restrict__ x,
                                                const float* __restrict__ rw) {
    __shared__ float srw[NE * DIM];          // 64 KB router weights
    __shared__ float s_pi[NE];
    __shared__ int   s_cnt[NE];
    int tid = threadIdx.x;
    if (tid < NE) { s_pi[tid] = 0.f; s_cnt[tid] = 0; }
    for (int i = tid; i < NE * DIM; i += 256) srw[i] = rw[i];
    __syncthreads();

    int warp = tid >> 5, lane = tid & 31;
    int t = blockIdx.x * 8 + warp;
    const float* xr = x + (size_t)t * DIM;

    float xv[32];
#pragma unroll
    for (int j = 0; j < 32; ++j) xv[j] = xr[lane + 32 * j];

    float logit[NE];
#pragma unroll
    for (int e = 0; e < NE; ++e) {
        float s = 0.f;
        const float* w = srw + e * DIM;
#pragma unroll
        for (int j = 0; j < 32; ++j) s += xv[j] * w[lane + 32 * j];
#pragma unroll
        for (int o = 16; o > 0; o >>= 1) s += __shfl_xor_sync(0xffffffffu, s, o);
        logit[e] = s;                        // all lanes hold full sum
    }

    // top-2 (distinct, lowest index wins ties like lax.top_k)
    int e1 = 0; float v1 = logit[0];
#pragma unroll
    for (int e = 1; e < NE; ++e) if (logit[e] > v1) { v1 = logit[e]; e1 = e; }
    int e2 = -1; float v2 = -3.4e38f;
#pragma unroll
    for (int e = 0; e < NE; ++e) if (e != e1 && logit[e] > v2) { v2 = logit[e]; e2 = e; }

    float w1 = 1.f / (1.f + expf(v2 - v1));  // softmax over {v1,v2}
    float w2 = 1.f - w1;

    // full softmax normalizer for pi
    float se = 0.f;
#pragma unroll
    for (int e = 0; e < NE; ++e) se += expf(logit[e] - v1);
    float inv_se = 1.f / se;

    if (lane == 0) {
        atomicAdd(&s_cnt[e1], 1);
        atomicAdd(&s_cnt[e2], 1);
        int p1 = atomicAdd(&g_ecount[e1], 1);
        int p2 = atomicAdd(&g_ecount[e2], 1);
        g_etok[e1 * TOK + p1] = t;  g_ewt[e1 * TOK + p1] = w1;
        g_etok[e2 * TOK + p2] = t;  g_ewt[e2 * TOK + p2] = w2;
        g_tk_e[2 * t] = e1;  g_tk_pos[2 * t] = p1;
        g_tk_e[2 * t + 1] = e2;  g_tk_pos[2 * t + 1] = p2;
#pragma unroll
        for (int e = 0; e < NE; ++e)
            atomicAdd(&s_pi[e], expf(logit[e] - v1) * inv_se);
    }
    __syncthreads();
    if (tid < NE) {
        atomicAdd(&g_pi[tid], s_pi[tid]);
        atomicAdd(&g_cnt[tid], s_cnt[tid]);
    }
}

// ---------------- expert offsets + aux loss ----------------
__global__ void k_offaux(float* __restrict__ aux_dst) {
    int off = 0;
    float a = 0.f;
    for (int e = 0; e < NE; ++e) {
        g_eoff[e] = off;
        off += g_ecount[e];
        a += (g_pi[e] / (float)TOK) * ((float)g_cnt[e] / (float)TOK);
    }
    *aux_dst = a;
}

// ---------------- shared-expert GEMM: out = X @ Wsum^T ----------------
__global__ void __launch_bounds__(256, 2) k_shared_gemm(const float* __restrict__ X,
                                                        float* __restrict__ out) {
    __shared__ float As[16][132];
    __shared__ float Bs[16][132];
    int tid = threadIdx.x;
    int tx = tid & 15, ty = tid >> 4;
    int row0 = blockIdx.y * 128, col0 = blockIdx.x * 128;
    int lr = tid >> 2;              // 0..63
    int lk = (tid & 3) * 4;         // 0,4,8,12

    float acc[8][8];
#pragma unroll
    for (int i = 0; i < 8; ++i)
#pragma unroll
        for (int j = 0; j < 8; ++j) acc[i][j] = 0.f;

    for (int k0 = 0; k0 < DIM; k0 += 16) {
#pragma unroll
        for (int it = 0; it < 2; ++it) {
            int r = lr + it * 64;
            float4 va = *(const float4*)(X + (size_t)(row0 + r) * DIM + k0 + lk);
            As[lk + 0][r] = va.x; As[lk + 1][r] = va.y;
            As[lk + 2][r] = va.z; As[lk + 3][r] = va.w;
            float4 vb = *(const float4*)(g_wsum + (size_t)(col0 + r) * DIM + k0 + lk);
            Bs[lk + 0][r] = vb.x; Bs[lk + 1][r] = vb.y;
            Bs[lk + 2][r] = vb.z; Bs[lk + 3][r] = vb.w;
        }
        __syncthreads();
#pragma unroll
        for (int k = 0; k < 16; ++k) {
            float4 a0 = *(const float4*)&As[k][ty * 8];
            float4 a1 = *(const float4*)&As[k][ty * 8 + 4];
            float4 b0 = *(const float4*)&Bs[k][tx * 8];
            float4 b1 = *(const float4*)&Bs[k][tx * 8 + 4];
            float a[8] = {a0.x, a0.y, a0.z, a0.w, a1.x, a1.y, a1.z, a1.w};
            float b[8] = {b0.x, b0.y, b0.z, b0.w, b1.x, b1.y, b1.z, b1.w};
#pragma unroll
            for (int i = 0; i < 8; ++i)
#pragma unroll
                for (int j = 0; j < 8; ++j) acc[i][j] += a[i] * b[j];
        }
        __syncthreads();
    }

#pragma unroll
    for (int i = 0; i < 8; ++i) {
        int row = row0 + ty * 8 + i;
        float* dst = out + (size_t)row * DIM + col0 + tx * 8;
        float4 v0 = make_float4(acc[i][0], acc[i][1], acc[i][2], acc[i][3]);
        float4 v1 = make_float4(acc[i][4], acc[i][5], acc[i][6], acc[i][7]);
        *(float4*)(dst) = v0;
        *(float4*)(dst + 4) = v1;
    }
}

// ---------------- grouped expert GEMM (gathered rows, weighted output) ----------------
__global__ void __launch_bounds__(256, 2) k_expert_gemm(const float* __restrict__ X,
                                                        const float* __restrict__ EW) {
    int e = blockIdx.z;
    int n = g_ecount[e];
    int row0 = blockIdx.y * 128;
    if (row0 >= n) return;
    int col0 = blockIdx.x * 128;
    const float* W = EW + (size_t)e * DIM * DIM;

    __shared__ float As[16][132];
    __shared__ float Bs[16][132];
    int tid = threadIdx.x;
    int tx = tid & 15, ty = tid >> 4;
    int lr = tid >> 2;
    int lk = (tid & 3) * 4;

    // pre-gather this thread's two row token ids
    int tokA = (row0 + lr < n) ? g_etok[e * TOK + row0 + lr] : -1;
    int tokB = (row0 + lr + 64 < n) ? g_etok[e * TOK + row0 + lr + 64] : -1;

    float acc[8][8];
#pragma unroll
    for (int i = 0; i < 8; ++i)
#pragma unroll
        for (int j = 0; j < 8; ++j) acc[i][j] = 0.f;

    for (int k0 = 0; k0 < DIM; k0 += 16) {
#pragma unroll
        for (int it = 0; it < 2; ++it) {
            int r = lr + it * 64;
            int tk = it ? tokB : tokA;
            float4 va = make_float4(0.f, 0.f, 0.f, 0.f);
            if (tk >= 0)
                va = *(const float4*)(X + (size_t)tk * DIM + k0 + lk);
            As[lk + 0][r] = va.x; As[lk + 1][r] = va.y;
            As[lk + 2][r] = va.z; As[lk + 3][r] = va.w;
            float4 vb = *(const float4*)(W + (size_t)(col0 + r) * DIM + k0 + lk);
            Bs[lk + 0][r] = vb.x; Bs[lk + 1][r] = vb.y;
            Bs[lk + 2][r] = vb.z; Bs[lk + 3][r] = vb.w;
        }
        __syncthreads();
#pragma unroll
        for (int k = 0; k < 16; ++k) {
            float4 a0 = *(const float4*)&As[k][ty * 8];
            float4 a1 = *(const float4*)&As[k][ty * 8 + 4];
            float4 b0 = *(const float4*)&Bs[k][tx * 8];
            float4 b1 = *(const float4*)&Bs[k][tx * 8 + 4];
            float a[8] = {a0.x, a0.y, a0.z, a0.w, a1.x, a1.y, a1.z, a1.w};
            float b[8] = {b0.x, b0.y, b0.z, b0.w, b1.x, b1.y, b1.z, b1.w};
#pragma unroll
            for (int i = 0; i < 8; ++i)
#pragma unroll
                for (int j = 0; j < 8; ++j) acc[i][j] += a[i] * b[j];
        }
        __syncthreads();
    }

    int base = g_eoff[e] + row0;
#pragma unroll
    for (int i = 0; i < 8; ++i) {
        int r = ty * 8 + i;
        if (row0 + r < n) {
            float wt = g_ewt[e * TOK + row0 + r];
            float* dst = g_eout + (size_t)(base + r) * DIM + col0 + tx * 8;
            float4 v0 = make_float4(acc[i][0] * wt, acc[i][1] * wt,
                                    acc[i][2] * wt, acc[i][3] * wt);
            float4 v1 = make_float4(acc[i][4] * wt, acc[i][5] * wt,
                                    acc[i][6] * wt, acc[i][7] * wt);
            *(float4*)(dst) = v0;
            *(float4*)(dst + 4) = v1;
        }
    }
}

// ---------------- combine: out += eout[slot1] + eout[slot2] ----------------
__global__ void k_combine(float* __restrict__ out) {
    int idx = blockIdx.x * 256 + threadIdx.x;   // over TOK*DIM/4
    int t = idx >> 8;                            // DIM/4 = 256 float4 per row
    int c = (idx & 255) << 2;
    int s1 = g_eoff[g_tk_e[2 * t]] + g_tk_pos[2 * t];
    int s2 = g_eoff[g_tk_e[2 * t + 1]] + g_tk_pos[2 * t + 1];
    float4 o = *(float4*)(out + (size_t)t * DIM + c);
    float4 a = *(const float4*)(g_eout + (size_t)s1 * DIM + c);
    float4 b = *(const float4*)(g_eout + (size_t)s2 * DIM + c);
    o.x += a.x + b.x;
    o.y += a.y + b.y;
    o.z += a.z + b.z;
    o.w += a.w + b.w;
    *(float4*)(out + (size_t)t * DIM + c) = o;
}

// ---------------- launch ----------------
extern "C" void kernel_launch(void* const* d_in, const int* in_sizes, int n_in,
                              void* d_out, int out_size) {
    const float* feat = (const float*)d_in[0];
    const float* rw   = (const float*)d_in[1];
    const float* sw   = (const float*)d_in[2];
    const float* ew   = (const float*)d_in[3];
    float* out = (float*)d_out;

    k_reset<<<1, 32>>>();
    k_wsum<<<(DIM * DIM / 4) / 256, 256>>>(sw);
    k_router<<<TOK / 8, 256>>>(feat, rw);
    k_offaux<<<1, 1>>>(out + (out_size - 1));
    k_shared_gemm<<<dim3(8, 64), 256>>>(feat, out);
    k_expert_gemm<<<dim3(8, 64, NE), 256>>>(feat, ew);
    k_combine<<<(TOK * DIM / 4) / 256, 256>>>(out);
}

// round 3
// speedup vs baseline: 3.1136x; 3.1136x over previous
#include <cuda_runtime.h>
#include <math.h>
#include <stdint.h>

#define TOK 8192
#define DIM 1024
#define NE  16

// ---------------- device scratch (static, allocation-free) ----------------
__device__ __align__(1024) float g_wsum[DIM * DIM];              // folded shared weight (4 MB)
__device__ __align__(1024) float g_xg[(2 * TOK + 128) * DIM];    // gathered expert rows (+pad)
__device__ __align__(1024) float g_eout[3 * TOK * DIM];          // expert+shared outputs (96 MB)
__device__ int   g_ecount[NE];
__device__ int   g_eoff[NE + 1];
__device__ float g_pi[NE];
__device__ int   g_cnt[NE];
__device__ int   g_etok[NE * TOK];
__device__ float g_ewt[NE * TOK];
__device__ int   g_tk_e[TOK * 2];
__device__ int   g_tk_pos[TOK * 2];

__device__ __forceinline__ uint32_t smem_u32(const void* p) {
    uint32_t a;
    asm("{ .reg .u64 t; cvta.to.shared.u64 t, %1; cvt.u32.u64 %0, t; }" : "=r"(a) : "l"(p));
    return a;
}

#define CP16(dst, src) \
    asm volatile("cp.async.cg.shared.global [%0], [%1], 16;" :: "r"(dst), "l"(src) : "memory")
#define CP_COMMIT() asm volatile("cp.async.commit_group;" ::: "memory")
#define CP_WAIT1()  asm volatile("cp.async.wait_group 1;" ::: "memory")

__device__ __forceinline__ uint32_t f2tf32(uint32_t x) {
    uint32_t r;
    asm("cvt.rna.tf32.f32 %0, %1;" : "=r"(r) : "f"(__uint_as_float(x)));
    return r;
}

// ---------------- small kernels ----------------
__global__ void k_reset() {
    int i = threadIdx.x;
    if (i < NE) { g_ecount[i] = 0; g_pi[i] = 0.f; g_cnt[i] = 0; }
}

__global__ void k_wsum(const float* __restrict__ sw) {
    int i = blockIdx.x * 256 + threadIdx.x;
    const float4* s4 = (const float4*)sw;
    float4 a = s4[i];
    float4 b = s4[i + (DIM * DIM) / 4];
    ((float4*)g_wsum)[i] = make_float4(a.x + b.x, a.y + b.y, a.z + b.z, a.w + b.w);
}

__global__ void __launch_bounds__(256) k_router(const float* __restrict__ x,
                                                const float* __restrict__ rw) {
    __shared__ float srw[NE * DIM];
    __shared__ float s_pi[NE];
    __shared__ int   s_cnt[NE];
    int tid = threadIdx.x;
    if (tid < NE) { s_pi[tid] = 0.f; s_cnt[tid] = 0; }
    for (int i = tid; i < NE * DIM; i += 256) srw[i] = rw[i];
    __syncthreads();

    int warp = tid >> 5, lane = tid & 31;
    int t = blockIdx.x * 8 + warp;
    const float* xr = x + (size_t)t * DIM;

    float xv[32];
#pragma unroll
    for (int j = 0; j < 32; ++j) xv[j] = xr[lane + 32 * j];

    float logit[NE];
#pragma unroll
    for (int e = 0; e < NE; ++e) {
        float s = 0.f;
        const float* w = srw + e * DIM;
#pragma unroll
        for (int j = 0; j < 32; ++j) s += xv[j] * w[lane + 32 * j];
#pragma unroll
        for (int o = 16; o > 0; o >>= 1) s += __shfl_xor_sync(0xffffffffu, s, o);
        logit[e] = s;
    }

    int e1 = 0; float v1 = logit[0];
#pragma unroll
    for (int e = 1; e < NE; ++e) if (logit[e] > v1) { v1 = logit[e]; e1 = e; }
    int e2 = -1; float v2 = -3.4e38f;
#pragma unroll
    for (int e = 0; e < NE; ++e) if (e != e1 && logit[e] > v2) { v2 = logit[e]; e2 = e; }

    float w1 = 1.f / (1.f + expf(v2 - v1));
    float w2 = 1.f - w1;

    float se = 0.f;
#pragma unroll
    for (int e = 0; e < NE; ++e) se += expf(logit[e] - v1);
    float inv_se = 1.f / se;

    if (lane == 0) {
        atomicAdd(&s_cnt[e1], 1);
        atomicAdd(&s_cnt[e2], 1);
        int p1 = atomicAdd(&g_ecount[e1], 1);
        int p2 = atomicAdd(&g_ecount[e2], 1);
        g_etok[e1 * TOK + p1] = t;  g_ewt[e1 * TOK + p1] = w1;
        g_etok[e2 * TOK + p2] = t;  g_ewt[e2 * TOK + p2] = w2;
        g_tk_e[2 * t] = e1;  g_tk_pos[2 * t] = p1;
        g_tk_e[2 * t + 1] = e2;  g_tk_pos[2 * t + 1] = p2;
#pragma unroll
        for (int e = 0; e < NE; ++e)
            atomicAdd(&s_pi[e], expf(logit[e] - v1) * inv_se);
    }
    __syncthreads();
    if (tid < NE) {
        atomicAdd(&g_pi[tid], s_pi[tid]);
        atomicAdd(&g_cnt[tid], s_cnt[tid]);
    }
}

__global__ void k_offaux(float* __restrict__ aux_dst) {
    int off = 0;
    float a = 0.f;
    for (int e = 0; e < NE; ++e) {
        g_eoff[e] = off;
        off += g_ecount[e];
        a += (g_pi[e] / (float)TOK) * ((float)g_cnt[e] / (float)TOK);
    }
    g_eoff[NE] = 2 * TOK;
    *aux_dst = a;
}

__global__ void k_gather(const float* __restrict__ X) {
    __shared__ int s_tok;
    int slot = blockIdx.x;
    if (threadIdx.x == 0) {
        int e = 0;
#pragma unroll
        for (int i = 1; i < NE; ++i) if (slot >= g_eoff[i]) e = i;
        s_tok = g_etok[e * TOK + (slot - g_eoff[e])];
    }
    __syncthreads();
    int tok = s_tok;
    float4 v = *(const float4*)(X + (size_t)tok * DIM + threadIdx.x * 4);
    *(float4*)(g_xg + (size_t)slot * DIM + threadIdx.x * 4) = v;
}

// ---------------- tf32 mma.sync grouped GEMM ----------------
// CTA tile 128x128, K=32/stage, 2-stage cp.async double buffer.
// 8 warps: wm = wid&1 (M), wn = wid>>1 (N); warp tile 64x32.
// smem tiles stored K-major with 36-float (144B) row stride.
#define RSTR    36
#define A_BYTES (128 * RSTR * 4)
#define STG_B   (2 * A_BYTES)
#define SMEM_SZ (2 * STG_B)

__global__ void __launch_bounds__(256, 2) k_gemm(const float* __restrict__ Xfeat,
                                                 const float* __restrict__ EW) {
    int g = blockIdx.z;
    int n = (g < NE) ? g_ecount[g] : TOK;
    int row0 = blockIdx.y * 128;
    if (row0 >= n) return;
    int col0 = blockIdx.x * 128;
    int goff = g_eoff[g];

    const float* Abase = (g < NE) ? (g_xg + (size_t)(goff + row0) * DIM)
                                  : (Xfeat + (size_t)row0 * DIM);
    const float* Bbase = (g < NE) ? (EW + (size_t)g * DIM * DIM + (size_t)col0 * DIM)
                                  : (g_wsum + (size_t)col0 * DIM);

    extern __shared__ __align__(1024) char smem[];
    uint32_t sb = smem_u32(smem);
    int tid = threadIdx.x;
    int wid = tid >> 5, lane = tid & 31;
    int wm = wid & 1, wn = wid >> 1;

    // per-thread cp.async coords
    int ldrow = tid >> 3;            // 0..31
    int ldch = (tid & 7) * 16;       // byte chunk 0..112

    // ldmatrix lane addressing
    int lt = lane & 7, mat = lane >> 3;
    int rA = ((mat & 1) << 3) + lt;
    int cA = (mat >> 1) << 2;
    int rB = ((mat >> 1) << 3) + lt;
    int cB = (mat & 1) << 2;
    uint32_t aA0 = sb + (uint32_t)(((wm * 64 + rA) * RSTR + cA) * 4);
    uint32_t aB0 = sb + (uint32_t)A_BYTES + (uint32_t)(((wn * 32 + rB) * RSTR + cB) * 4);

    float acc[4][4][4];
#pragma unroll
    for (int i = 0; i < 4; ++i)
#pragma unroll
        for (int j = 0; j < 4; ++j)
#pragma unroll
            for (int k = 0; k < 4; ++k) acc[i][j][k] = 0.f;

    // prologue: stage 0
    {
        uint32_t so = sb;
#pragma unroll
        for (int i = 0; i < 4; ++i) {
            int r = ldrow + i * 32;
            CP16(so + (uint32_t)(r * 144 + ldch),
                 (const char*)Abase + (size_t)r * 4096 + ldch);
            CP16(so + (uint32_t)A_BYTES + (uint32_t)(r * 144 + ldch),
                 (const char*)Bbase + (size_t)r * 4096 + ldch);
        }
        CP_COMMIT();
    }

    for (int ks = 0; ks < DIM / 32; ++ks) {
        // issue next stage
        if (ks + 1 < DIM / 32) {
            uint32_t so = sb + (uint32_t)(((ks + 1) & 1) * STG_B);
            int kb = (ks + 1) * 128;   // byte offset into K
#pragma unroll
            for (int i = 0; i < 4; ++i) {
                int r = ldrow + i * 32;
                CP16(so + (uint32_t)(r * 144 + ldch),
                     (const char*)Abase + (size_t)r * 4096 + kb + ldch);
                CP16(so + (uint32_t)A_BYTES + (uint32_t)(r * 144 + ldch),
                     (const char*)Bbase + (size_t)r * 4096 + kb + ldch);
            }
        }
        CP_COMMIT();
        CP_WAIT1();
        __syncthreads();

        uint32_t stg = (uint32_t)((ks & 1) * STG_B);
#pragma unroll
        for (int sub = 0; sub < 4; ++sub) {
            uint32_t af[4][4];
            uint32_t bf[4][2];
#pragma unroll
            for (int mt = 0; mt < 4; ++mt) {
                uint32_t addr = aA0 + stg + (uint32_t)(mt * 16 * RSTR * 4 + sub * 32);
                asm volatile("ldmatrix.sync.aligned.m8n8.x4.shared.b16 {%0,%1,%2,%3}, [%4];"
                    : "=r"(af[mt][0]), "=r"(af[mt][1]), "=r"(af[mt][2]), "=r"(af[mt][3])
                    : "r"(addr));
            }
#pragma unroll
            for (int p = 0; p < 2; ++p) {
                uint32_t addr = aB0 + stg + (uint32_t)(p * 16 * RSTR * 4 + sub * 32);
                asm volatile("ldmatrix.sync.aligned.m8n8.x4.shared.b16 {%0,%1,%2,%3}, [%4];"
                    : "=r"(bf[2 * p][0]), "=r"(bf[2 * p][1]),
                      "=r"(bf[2 * p + 1][0]), "=r"(bf[2 * p + 1][1])
                    : "r"(addr));
            }
#pragma unroll
            for (int mt = 0; mt < 4; ++mt)
#pragma unroll
                for (int q = 0; q < 4; ++q) af[mt][q] = f2tf32(af[mt][q]);
#pragma unroll
            for (int nt = 0; nt < 4; ++nt) {
                bf[nt][0] = f2tf32(bf[nt][0]);
                bf[nt][1] = f2tf32(bf[nt][1]);
            }
#pragma unroll
            for (int mt = 0; mt < 4; ++mt)
#pragma unroll
                for (int nt = 0; nt < 4; ++nt) {
                    asm volatile(
                        "mma.sync.aligned.m16n8k8.row.col.f32.tf32.tf32.f32 "
                        "{%0,%1,%2,%3}, {%4,%5,%6,%7}, {%8,%9}, {%0,%1,%2,%3};"
                        : "+f"(acc[mt][nt][0]), "+f"(acc[mt][nt][1]),
                          "+f"(acc[mt][nt][2]), "+f"(acc[mt][nt][3])
                        : "r"(af[mt][0]), "r"(af[mt][1]), "r"(af[mt][2]), "r"(af[mt][3]),
                          "r"(bf[nt][0]), "r"(bf[nt][1]));
                }
        }
        __syncthreads();
    }

    // epilogue: weight + store to g_eout
    int t4 = lane >> 2, t2 = lane & 3;
#pragma unroll
    for (int mt = 0; mt < 4; ++mt) {
#pragma unroll
        for (int h = 0; h < 2; ++h) {
            int rowT = wm * 64 + mt * 16 + h * 8 + t4;        // row within 128-tile
            int gr = row0 + rowT;                             // row within group
            bool valid = (g >= NE) || (gr < n);
            float wt = 1.f;
            if (g < NE && valid) wt = g_ewt[g * TOK + gr];
            if (valid) {
                float* dst = g_eout + (size_t)(goff + gr) * DIM + col0 + wn * 32 + t2 * 2;
#pragma unroll
                for (int nt = 0; nt < 4; ++nt) {
                    float2 v = make_float2(acc[mt][nt][2 * h] * wt,
                                           acc[mt][nt][2 * h + 1] * wt);
                    *(float2*)(dst + nt * 8) = v;
                }
            }
        }
    }
}

// ---------------- combine ----------------
__global__ void k_combine(float* __restrict__ out) {
    int idx = blockIdx.x * 256 + threadIdx.x;
    int t = idx >> 8;
    int c = (idx & 255) << 2;
    int s0 = 2 * TOK + t;
    int s1 = g_eoff[g_tk_e[2 * t]] + g_tk_pos[2 * t];
    int s2 = g_eoff[g_tk_e[2 * t + 1]] + g_tk_pos[2 * t + 1];
    float4 a = *(const float4*)(g_eout + (size_t)s0 * DIM + c);
    float4 b = *(const float4*)(g_eout + (size_t)s1 * DIM + c);
    float4 d = *(const float4*)(g_eout + (size_t)s2 * DIM + c);
    *(float4*)(out + (size_t)t * DIM + c) =
        make_float4(a.x + b.x + d.x, a.y + b.y + d.y, a.z + b.z + d.z, a.w + b.w + d.w);
}

// ---------------- launch ----------------
extern "C" void kernel_launch(void* const* d_in, const int* in_sizes, int n_in,
                              void* d_out, int out_size) {
    const float* feat = (const float*)d_in[0];
    const float* rw   = (const float*)d_in[1];
    const float* sw   = (const float*)d_in[2];
    const float* ew   = (const float*)d_in[3];
    float* out = (float*)d_out;

    cudaFuncSetAttribute(k_gemm, cudaFuncAttributeMaxDynamicSharedMemorySize, SMEM_SZ);

    k_reset<<<1, 32>>>();
    k_wsum<<<(DIM * DIM / 4) / 256, 256>>>(sw);
    k_router<<<TOK / 8, 256>>>(feat, rw);
    k_offaux<<<1, 1>>>(out + (out_size - 1));
    k_gather<<<2 * TOK, 256>>>(feat);
    k_gemm<<<dim3(DIM / 128, TOK / 128, NE + 1), 256, SMEM_SZ>>>(feat, ew);
    k_combine<<<(TOK * DIM / 4) / 256, 256>>>(out);
}

// round 4
// speedup vs baseline: 3.2607x; 1.0473x over previous
#include <cuda_runtime.h>
#include <math.h>
#include <stdint.h>

#define TOK 8192
#define DIM 1024
#define NE  16

// ---------------- device scratch (static, allocation-free) ----------------
__device__ __align__(1024) float g_wsum[DIM * DIM];              // folded+rounded shared weight (4 MB)
__device__ __align__(1024) float g_xf[TOK * DIM];                // rounded feat (32 MB)
__device__ __align__(1024) float g_xg[(2 * TOK + 128) * DIM];    // gathered rounded rows (+pad)
__device__ __align__(1024) float g_ewr[NE * DIM * DIM];          // rounded expert weights (64 MB)
__device__ __align__(1024) float g_eout[2 * TOK * DIM];          // expert outputs (64 MB)
__device__ int   g_ecount[NE];
__device__ int   g_eoff[NE + 1];
__device__ float g_pi[NE];
__device__ int   g_cnt[NE];
__device__ int   g_etok[NE * TOK];
__device__ float g_ewt[NE * TOK];
__device__ int   g_tk_e[TOK * 2];
__device__ int   g_tk_pos[TOK * 2];

__device__ __forceinline__ uint32_t smem_u32(const void* p) {
    uint32_t a;
    asm("{ .reg .u64 t; cvta.to.shared.u64 t, %1; cvt.u32.u64 %0, t; }" : "=r"(a) : "l"(p));
    return a;
}

#define CP16(dst, src) \
    asm volatile("cp.async.cg.shared.global [%0], [%1], 16;" :: "r"(dst), "l"(src) : "memory")
#define CP_COMMIT() asm volatile("cp.async.commit_group;" ::: "memory")
#define CP_WAIT1()  asm volatile("cp.async.wait_group 1;" ::: "memory")

__device__ __forceinline__ float f2tf32f(float x) {
    uint32_t r;
    asm("cvt.rna.tf32.f32 %0, %1;" : "=r"(r) : "f"(x));
    return __uint_as_float(r);
}

// ---------------- small kernels ----------------
// fold shared_w + round; block 0 also resets counters
__global__ void k_wsum(const float* __restrict__ sw) {
    int tid = threadIdx.x;
    if (blockIdx.x == 0 && tid < NE) { g_ecount[tid] = 0; g_pi[tid] = 0.f; g_cnt[tid] = 0; }
    int i = blockIdx.x * 256 + tid;
    const float4* s4 = (const float4*)sw;
    float4 a = s4[i];
    float4 b = s4[i + (DIM * DIM) / 4];
    ((float4*)g_wsum)[i] = make_float4(f2tf32f(a.x + b.x), f2tf32f(a.y + b.y),
                                       f2tf32f(a.z + b.z), f2tf32f(a.w + b.w));
}

// round expert weights
__global__ void k_ewround(const float* __restrict__ ew) {
    int i = blockIdx.x * 256 + threadIdx.x;
    float4 v = ((const float4*)ew)[i];
    ((float4*)g_ewr)[i] = make_float4(f2tf32f(v.x), f2tf32f(v.y), f2tf32f(v.z), f2tf32f(v.w));
}

__global__ void __launch_bounds__(256) k_router(const float* __restrict__ x,
                                                const float* __restrict__ rw) {
    __shared__ float srw[NE * DIM];
    __shared__ float s_pi[NE];
    __shared__ int   s_cnt[NE];
    int tid = threadIdx.x;
    if (tid < NE) { s_pi[tid] = 0.f; s_cnt[tid] = 0; }
    for (int i = tid; i < NE * DIM; i += 256) srw[i] = rw[i];
    __syncthreads();

    int warp = tid >> 5, lane = tid & 31;
    int t = blockIdx.x * 8 + warp;
    const float* xr = x + (size_t)t * DIM;

    float xv[32];
#pragma unroll
    for (int j = 0; j < 32; ++j) xv[j] = xr[lane + 32 * j];

    // write rounded copy of feat for the GEMMs
#pragma unroll
    for (int j = 0; j < 32; ++j) g_xf[(size_t)t * DIM + lane + 32 * j] = f2tf32f(xv[j]);

    float logit[NE];
#pragma unroll
    for (int e = 0; e < NE; ++e) {
        float s = 0.f;
        const float* w = srw + e * DIM;
#pragma unroll
        for (int j = 0; j < 32; ++j) s += xv[j] * w[lane + 32 * j];
#pragma unroll
        for (int o = 16; o > 0; o >>= 1) s += __shfl_xor_sync(0xffffffffu, s, o);
        logit[e] = s;
    }

    int e1 = 0; float v1 = logit[0];
#pragma unroll
    for (int e = 1; e < NE; ++e) if (logit[e] > v1) { v1 = logit[e]; e1 = e; }
    int e2 = -1; float v2 = -3.4e38f;
#pragma unroll
    for (int e = 0; e < NE; ++e) if (e != e1 && logit[e] > v2) { v2 = logit[e]; e2 = e; }

    float w1 = 1.f / (1.f + expf(v2 - v1));
    float w2 = 1.f - w1;

    float se = 0.f;
#pragma unroll
    for (int e = 0; e < NE; ++e) se += expf(logit[e] - v1);
    float inv_se = 1.f / se;

    if (lane == 0) {
        atomicAdd(&s_cnt[e1], 1);
        atomicAdd(&s_cnt[e2], 1);
        int p1 = atomicAdd(&g_ecount[e1], 1);
        int p2 = atomicAdd(&g_ecount[e2], 1);
        g_etok[e1 * TOK + p1] = t;  g_ewt[e1 * TOK + p1] = w1;
        g_etok[e2 * TOK + p2] = t;  g_ewt[e2 * TOK + p2] = w2;
        g_tk_e[2 * t] = e1;  g_tk_pos[2 * t] = p1;
        g_tk_e[2 * t + 1] = e2;  g_tk_pos[2 * t + 1] = p2;
#pragma unroll
        for (int e = 0; e < NE; ++e)
            atomicAdd(&s_pi[e], expf(logit[e] - v1) * inv_se);
    }
    __syncthreads();
    if (tid < NE) {
        atomicAdd(&g_pi[tid], s_pi[tid]);
        atomicAdd(&g_cnt[tid], s_cnt[tid]);
    }
}

__global__ void k_offaux(float* __restrict__ aux_dst) {
    int off = 0;
    float a = 0.f;
    for (int e = 0; e < NE; ++e) {
        g_eoff[e] = off;
        off += g_ecount[e];
        a += (g_pi[e] / (float)TOK) * ((float)g_cnt[e] / (float)TOK);
    }
    g_eoff[NE] = 0;
    *aux_dst = a;
}

__global__ void k_gather() {
    __shared__ int s_tok;
    int slot = blockIdx.x;
    if (threadIdx.x == 0) {
        int e = 0;
#pragma unroll
        for (int i = 1; i < NE; ++i) if (slot >= g_eoff[i]) e = i;
        s_tok = g_etok[e * TOK + (slot - g_eoff[e])];
    }
    __syncthreads();
    int tok = s_tok;
    float4 v = *(const float4*)(g_xf + (size_t)tok * DIM + threadIdx.x * 4);
    *(float4*)(g_xg + (size_t)slot * DIM + threadIdx.x * 4) = v;
}

// ---------------- tf32 mma.sync grouped GEMM (pre-rounded operands) ----------------
// CTA tile 128x128, K=32/stage, 3-stage cp.async pipeline, one sync per K-step.
#define RSTR    36
#define A_BYTES (128 * RSTR * 4)
#define STG_B   (2 * A_BYTES)
#define NSTG    3
#define SMEM_SZ (NSTG * STG_B)
#define NK      (DIM / 32)

__global__ void __launch_bounds__(256, 2) k_gemm(float* __restrict__ out) {
    int g = blockIdx.z;
    int n = (g < NE) ? g_ecount[g] : TOK;
    int row0 = blockIdx.y * 128;
    if (row0 >= n) return;
    int col0 = blockIdx.x * 128;
    int goff = g_eoff[g];

    const float* Abase = (g < NE) ? (g_xg + (size_t)(goff + row0) * DIM)
                                  : (g_xf + (size_t)row0 * DIM);
    const float* Bbase = (g < NE) ? (g_ewr + (size_t)g * DIM * DIM + (size_t)col0 * DIM)
                                  : (g_wsum + (size_t)col0 * DIM);

    extern __shared__ __align__(1024) char smem[];
    uint32_t sb = smem_u32(smem);
    int tid = threadIdx.x;
    int wid = tid >> 5, lane = tid & 31;
    int wm = wid & 1, wn = wid >> 1;

    int ldrow = tid >> 3;
    int ldch = (tid & 7) * 16;

    int lt = lane & 7, mat = lane >> 3;
    int rA = ((mat & 1) << 3) + lt;
    int cA = (mat >> 1) << 2;
    int rB = ((mat >> 1) << 3) + lt;
    int cB = (mat & 1) << 2;
    uint32_t aA0 = sb + (uint32_t)(((wm * 64 + rA) * RSTR + cA) * 4);
    uint32_t aB0 = sb + (uint32_t)A_BYTES + (uint32_t)(((wn * 32 + rB) * RSTR + cB) * 4);

    float acc[4][4][4];
#pragma unroll
    for (int i = 0; i < 4; ++i)
#pragma unroll
        for (int j = 0; j < 4; ++j)
#pragma unroll
            for (int k = 0; k < 4; ++k) acc[i][j][k] = 0.f;

    // prologue: stages 0,1
#pragma unroll
    for (int st = 0; st < 2; ++st) {
        uint32_t so = sb + (uint32_t)(st * STG_B);
        int kb = st * 128;
#pragma unroll
        for (int i = 0; i < 4; ++i) {
            int r = ldrow + i * 32;
            CP16(so + (uint32_t)(r * 144 + ldch),
                 (const char*)Abase + (size_t)r * 4096 + kb + ldch);
            CP16(so + (uint32_t)A_BYTES + (uint32_t)(r * 144 + ldch),
                 (const char*)Bbase + (size_t)r * 4096 + kb + ldch);
        }
        CP_COMMIT();
    }

    for (int ks = 0; ks < NK; ++ks) {
        CP_WAIT1();
        __syncthreads();

        // issue stage ks+2 (buffer (ks-1)%3 — safe: sync proved compute ks-1 done everywhere)
        if (ks + 2 < NK) {
            uint32_t so = sb + (uint32_t)(((ks + 2) % NSTG) * STG_B);
            int kb = (ks + 2) * 128;
#pragma unroll
            for (int i = 0; i < 4; ++i) {
                int r = ldrow + i * 32;
                CP16(so + (uint32_t)(r * 144 + ldch),
                     (const char*)Abase + (size_t)r * 4096 + kb + ldch);
                CP16(so + (uint32_t)A_BYTES + (uint32_t)(r * 144 + ldch),
                     (const char*)Bbase + (size_t)r * 4096 + kb + ldch);
            }
        }
        CP_COMMIT();

        uint32_t stg = (uint32_t)((ks % NSTG) * STG_B);
#pragma unroll
        for (int sub = 0; sub < 4; ++sub) {
            uint32_t af[4][4];
            uint32_t bf[4][2];
#pragma unroll
            for (int mt = 0; mt < 4; ++mt) {
                uint32_t addr = aA0 + stg + (uint32_t)(mt * 16 * RSTR * 4 + sub * 32);
                asm volatile("ldmatrix.sync.aligned.m8n8.x4.shared.b16 {%0,%1,%2,%3}, [%4];"
                    : "=r"(af[mt][0]), "=r"(af[mt][1]), "=r"(af[mt][2]), "=r"(af[mt][3])
                    : "r"(addr));
            }
#pragma unroll
            for (int p = 0; p < 2; ++p) {
                uint32_t addr = aB0 + stg + (uint32_t)(p * 16 * RSTR * 4 + sub * 32);
                asm volatile("ldmatrix.sync.aligned.m8n8.x4.shared.b16 {%0,%1,%2,%3}, [%4];"
                    : "=r"(bf[2 * p][0]), "=r"(bf[2 * p][1]),
                      "=r"(bf[2 * p + 1][0]), "=r"(bf[2 * p + 1][1])
                    : "r"(addr));
            }
#pragma unroll
            for (int mt = 0; mt < 4; ++mt)
#pragma unroll
                for (int nt = 0; nt < 4; ++nt) {
                    asm volatile(
                        "mma.sync.aligned.m16n8k8.row.col.f32.tf32.tf32.f32 "
                        "{%0,%1,%2,%3}, {%4,%5,%6,%7}, {%8,%9}, {%0,%1,%2,%3};"
                        : "+f"(acc[mt][nt][0]), "+f"(acc[mt][nt][1]),
                          "+f"(acc[mt][nt][2]), "+f"(acc[mt][nt][3])
                        : "r"(af[mt][0]), "r"(af[mt][1]), "r"(af[mt][2]), "r"(af[mt][3]),
                          "r"(bf[nt][0]), "r"(bf[nt][1]));
                }
        }
    }

    // epilogue
    int t4 = lane >> 2, t2 = lane & 3;
#pragma unroll
    for (int mt = 0; mt < 4; ++mt) {
#pragma unroll
        for (int h = 0; h < 2; ++h) {
            int rowT = wm * 64 + mt * 16 + h * 8 + t4;
            int gr = row0 + rowT;
            if (g >= NE) {
                float* dst = out + (size_t)gr * DIM + col0 + wn * 32 + t2 * 2;
#pragma unroll
                for (int nt = 0; nt < 4; ++nt)
                    *(float2*)(dst + nt * 8) =
                        make_float2(acc[mt][nt][2 * h], acc[mt][nt][2 * h + 1]);
            } else if (gr < n) {
                float wt = g_ewt[g * TOK + gr];
                float* dst = g_eout + (size_t)(goff + gr) * DIM + col0 + wn * 32 + t2 * 2;
#pragma unroll
                for (int nt = 0; nt < 4; ++nt)
                    *(float2*)(dst + nt * 8) =
                        make_float2(acc[mt][nt][2 * h] * wt, acc[mt][nt][2 * h + 1] * wt);
            }
        }
    }
}

// ---------------- combine: out += eout[s1] + eout[s2] ----------------
__global__ void k_combine(float* __restrict__ out) {
    int idx = blockIdx.x * 256 + threadIdx.x;
    int t = idx >> 8;
    int c = (idx & 255) << 2;
    int s1 = g_eoff[g_tk_e[2 * t]] + g_tk_pos[2 * t];
    int s2 = g_eoff[g_tk_e[2 * t + 1]] + g_tk_pos[2 * t + 1];
    float4 o = *(float4*)(out + (size_t)t * DIM + c);
    float4 b = *(const float4*)(g_eout + (size_t)s1 * DIM + c);
    float4 d = *(const float4*)(g_eout + (size_t)s2 * DIM + c);
    *(float4*)(out + (size_t)t * DIM + c) =
        make_float4(o.x + b.x + d.x, o.y + b.y + d.y, o.z + b.z + d.z, o.w + b.w + d.w);
}

// ---------------- launch ----------------
extern "C" void kernel_launch(void* const* d_in, const int* in_sizes, int n_in,
                              void* d_out, int out_size) {
    const float* feat = (const float*)d_in[0];
    const float* rw   = (const float*)d_in[1];
    const float* sw   = (const float*)d_in[2];
    const float* ew   = (const float*)d_in[3];
    float* out = (float*)d_out;

    cudaFuncSetAttribute(k_gemm, cudaFuncAttributeMaxDynamicSharedMemorySize, SMEM_SZ);

    k_wsum<<<(DIM * DIM / 4) / 256, 256>>>(sw);
    k_ewround<<<(NE * DIM * DIM / 4) / 256, 256>>>(ew);
    k_router<<<TOK / 8, 256>>>(feat, rw);
    k_offaux<<<1, 1>>>(out + (out_size - 1));
    k_gather<<<2 * TOK, 256>>>();
    k_gemm<<<dim3(DIM / 128, TOK / 128, NE + 1), 256, SMEM_SZ>>>(out);
    k_combine<<<(TOK * DIM / 4) / 256, 256>>>(out);
}

// round 5
// speedup vs baseline: 5.1429x; 1.5773x over previous
#include <cuda_runtime.h>
#include <cuda_fp16.h>
#include <math.h>
#include <stdint.h>

#define TOK 8192
#define DIM 1024
#define NE  16

// ---------------- device scratch (static, allocation-free) ----------------
__device__ __align__(1024) __half g_wsh[DIM * DIM];         // folded shared weight fp16 (2 MB)
__device__ __align__(1024) __half g_xh[TOK * DIM];          // fp16 feat (16 MB)
__device__ __align__(1024) __half g_ewh[NE * DIM * DIM];    // fp16 expert weights (32 MB)
__device__ int   g_ecount[NE];
__device__ float g_pi[NE];
__device__ int   g_cnt[NE];
__device__ int   g_etok[NE * TOK];
__device__ float g_ewt[NE * TOK];

__device__ __forceinline__ uint32_t smem_u32(const void* p) {
    uint32_t a;
    asm("{ .reg .u64 t; cvta.to.shared.u64 t, %1; cvt.u32.u64 %0, t; }" : "=r"(a) : "l"(p));
    return a;
}

#define CP16Z(dst, src, sz) \
    asm volatile("cp.async.cg.shared.global [%0], [%1], 16, %2;" \
        :: "r"(dst), "l"(src), "r"(sz) : "memory")
#define CP_COMMIT() asm volatile("cp.async.commit_group;" ::: "memory")
#define CP_WAIT1()  asm volatile("cp.async.wait_group 1;" ::: "memory")

// ---------------- small kernels ----------------
__global__ void k_zero(float* __restrict__ out, int n) {
    int i = blockIdx.x * 256 + threadIdx.x;
    if (i < n) out[i] = 0.f;
    if (blockIdx.x == 0 && threadIdx.x < NE) {
        g_ecount[threadIdx.x] = 0; g_pi[threadIdx.x] = 0.f; g_cnt[threadIdx.x] = 0;
    }
}

// fold shared_w -> fp16
__global__ void k_wsum(const float* __restrict__ sw) {
    int i = blockIdx.x * 256 + threadIdx.x;          // over DIM*DIM/4
    const float4* s4 = (const float4*)sw;
    float4 a = s4[i];
    float4 b = s4[i + (DIM * DIM) / 4];
    __half2 h0 = __floats2half2_rn(a.x + b.x, a.y + b.y);
    __half2 h1 = __floats2half2_rn(a.z + b.z, a.w + b.w);
    ((__half2*)g_wsh)[2 * i] = h0;
    ((__half2*)g_wsh)[2 * i + 1] = h1;
}

// expert weights -> fp16
__global__ void k_ewh(const float* __restrict__ ew) {
    int i = blockIdx.x * 256 + threadIdx.x;          // over NE*DIM*DIM/4
    float4 v = ((const float4*)ew)[i];
    ((__half2*)g_ewh)[2 * i] = __floats2half2_rn(v.x, v.y);
    ((__half2*)g_ewh)[2 * i + 1] = __floats2half2_rn(v.z, v.w);
}

__global__ void __launch_bounds__(256) k_router(const float* __restrict__ x,
                                                const float* __restrict__ rw) {
    __shared__ float srw[NE * DIM];
    __shared__ float s_pi[NE];
    __shared__ int   s_cnt[NE];
    int tid = threadIdx.x;
    if (tid < NE) { s_pi[tid] = 0.f; s_cnt[tid] = 0; }
    for (int i = tid; i < NE * DIM; i += 256) srw[i] = rw[i];
    __syncthreads();

    int warp = tid >> 5, lane = tid & 31;
    int t = blockIdx.x * 8 + warp;
    const float* xr = x + (size_t)t * DIM;

    float xv[32];
#pragma unroll
    for (int j = 0; j < 32; ++j) xv[j] = xr[lane + 32 * j];

    // fp16 copy of feat for the GEMMs
#pragma unroll
    for (int j = 0; j < 32; ++j)
        g_xh[(size_t)t * DIM + lane + 32 * j] = __float2half_rn(xv[j]);

    float logit[NE];
#pragma unroll
    for (int e = 0; e < NE; ++e) {
        float s = 0.f;
        const float* w = srw + e * DIM;
#pragma unroll
        for (int j = 0; j < 32; ++j) s += xv[j] * w[lane + 32 * j];
#pragma unroll
        for (int o = 16; o > 0; o >>= 1) s += __shfl_xor_sync(0xffffffffu, s, o);
        logit[e] = s;
    }

    int e1 = 0; float v1 = logit[0];
#pragma unroll
    for (int e = 1; e < NE; ++e) if (logit[e] > v1) { v1 = logit[e]; e1 = e; }
    int e2 = -1; float v2 = -3.4e38f;
#pragma unroll
    for (int e = 0; e < NE; ++e) if (e != e1 && logit[e] > v2) { v2 = logit[e]; e2 = e; }

    float w1 = 1.f / (1.f + expf(v2 - v1));
    float w2 = 1.f - w1;

    float se = 0.f;
#pragma unroll
    for (int e = 0; e < NE; ++e) se += expf(logit[e] - v1);
    float inv_se = 1.f / se;

    if (lane == 0) {
        atomicAdd(&s_cnt[e1], 1);
        atomicAdd(&s_cnt[e2], 1);
        int p1 = atomicAdd(&g_ecount[e1], 1);
        int p2 = atomicAdd(&g_ecount[e2], 1);
        g_etok[e1 * TOK + p1] = t;  g_ewt[e1 * TOK + p1] = w1;
        g_etok[e2 * TOK + p2] = t;  g_ewt[e2 * TOK + p2] = w2;
#pragma unroll
        for (int e = 0; e < NE; ++e)
            atomicAdd(&s_pi[e], expf(logit[e] - v1) * inv_se);
    }
    __syncthreads();
    if (tid < NE) {
        atomicAdd(&g_pi[tid], s_pi[tid]);
        atomicAdd(&g_cnt[tid], s_cnt[tid]);
    }
}

__global__ void k_offaux(float* __restrict__ aux_dst) {
    float a = 0.f;
    for (int e = 0; e < NE; ++e)
        a += (g_pi[e] / (float)TOK) * ((float)g_cnt[e] / (float)TOK);
    *aux_dst = a;
}

// ---------------- fp16 mma.sync grouped GEMM, gathered A, atomic epilogue ---------
// CTA tile 128x128, K-stage 64 halfs (128B/row), 3-stage cp.async pipeline.
// 8 warps: wm = wid&1 (64 M-rows), wn = wid>>1 (32 N-cols). 4 k16 subs per stage.
#define RSTRB   144
#define A_BYTES (128 * RSTRB)
#define STG_B   (2 * A_BYTES)
#define NSTG    3
#define SMEM_SZ (NSTG * STG_B)
#define NK      (DIM / 64)

__global__ void __launch_bounds__(256, 2) k_gemm(float* __restrict__ out) {
    int g = blockIdx.z;
    int n = (g < NE) ? g_ecount[g] : TOK;
    int row0 = blockIdx.y * 128;
    if (row0 >= n) return;
    int col0 = blockIdx.x * 128;

    const __half* Bbase = (g < NE) ? (g_ewh + (size_t)g * DIM * DIM + (size_t)col0 * DIM)
                                   : (g_wsh + (size_t)col0 * DIM);

    extern __shared__ __align__(1024) char smem[];
    uint32_t sb = smem_u32(smem);
    int tid = threadIdx.x;
    int wid = tid >> 5, lane = tid & 31;
    int wm = wid & 1, wn = wid >> 1;

    // loader coords: row = ldrow + i*32, 16B chunk ldch within the 128B K-slab
    int ldrow = tid >> 3;
    int ldch = (tid & 7) * 16;

    // A-row tokens (gathered) + validity
    int tk[4];
    uint32_t sz[4];
#pragma unroll
    for (int i = 0; i < 4; ++i) {
        int r = row0 + ldrow + i * 32;
        bool v = (r < n);
        tk[i] = (g < NE) ? (v ? g_etok[g * TOK + r] : 0) : r;
        sz[i] = v ? 16u : 0u;
    }

    // ldmatrix addressing
    int rA = lane & 15, cAb = lane >> 4;
    uint32_t aA0 = (uint32_t)(((wm * 64 + rA) * RSTRB) + cAb * 16);
    int rB = (lane & 7) + ((lane >> 4) << 3), cBb = (lane >> 3) & 1;
    uint32_t aB0 = (uint32_t)A_BYTES + (uint32_t)(((wn * 32 + rB) * RSTRB) + cBb * 16);

    float acc[4][4][4];
#pragma unroll
    for (int i = 0; i < 4; ++i)
#pragma unroll
        for (int j = 0; j < 4; ++j)
#pragma unroll
            for (int k = 0; k < 4; ++k) acc[i][j][k] = 0.f;

    // prologue: stages 0,1
#pragma unroll
    for (int st = 0; st < 2; ++st) {
        uint32_t so = sb + (uint32_t)(st * STG_B);
        int kb = st * 128;
#pragma unroll
        for (int i = 0; i < 4; ++i) {
            int r = ldrow + i * 32;
            CP16Z(so + (uint32_t)(r * RSTRB + ldch),
                  (const char*)g_xh + (size_t)tk[i] * 2048 + kb + ldch, sz[i]);
            CP16Z(so + (uint32_t)A_BYTES + (uint32_t)(r * RSTRB + ldch),
                  (const char*)Bbase + (size_t)r * 2048 + kb + ldch, 16u);
        }
        CP_COMMIT();
    }

    for (int ks = 0; ks < NK; ++ks) {
        CP_WAIT1();
        __syncthreads();

        if (ks + 2 < NK) {
            uint32_t so = sb + (uint32_t)(((ks + 2) % NSTG) * STG_B);
            int kb = (ks + 2) * 128;
#pragma unroll
            for (int i = 0; i < 4; ++i) {
                int r = ldrow + i * 32;
                CP16Z(so + (uint32_t)(r * RSTRB + ldch),
                      (const char*)g_xh + (size_t)tk[i] * 2048 + kb + ldch, sz[i]);
                CP16Z(so + (uint32_t)A_BYTES + (uint32_t)(r * RSTRB + ldch),
                      (const char*)Bbase + (size_t)r * 2048 + kb + ldch, 16u);
            }
        }
        CP_COMMIT();

        uint32_t stg = sb + (uint32_t)((ks % NSTG) * STG_B);
#pragma unroll
        for (int sub = 0; sub < 4; ++sub) {
            uint32_t af[4][4];
            uint32_t bf[4][2];
#pragma unroll
            for (int mt = 0; mt < 4; ++mt) {
                uint32_t addr = stg + aA0 + (uint32_t)(mt * 16 * RSTRB + sub * 32);
                asm volatile("ldmatrix.sync.aligned.m8n8.x4.shared.b16 {%0,%1,%2,%3}, [%4];"
                    : "=r"(af[mt][0]), "=r"(af[mt][1]), "=r"(af[mt][2]), "=r"(af[mt][3])
                    : "r"(addr));
            }
#pragma unroll
            for (int p = 0; p < 2; ++p) {
                uint32_t addr = stg + aB0 + (uint32_t)(p * 16 * RSTRB + sub * 32);
                asm volatile("ldmatrix.sync.aligned.m8n8.x4.shared.b16 {%0,%1,%2,%3}, [%4];"
                    : "=r"(bf[2 * p][0]), "=r"(bf[2 * p][1]),
                      "=r"(bf[2 * p + 1][0]), "=r"(bf[2 * p + 1][1])
                    : "r"(addr));
            }
#pragma unroll
            for (int mt = 0; mt < 4; ++mt)
#pragma unroll
                for (int nt = 0; nt < 4; ++nt) {
                    asm volatile(
                        "mma.sync.aligned.m16n8k16.row.col.f32.f16.f16.f32 "
                        "{%0,%1,%2,%3}, {%4,%5,%6,%7}, {%8,%9}, {%0,%1,%2,%3};"
                        : "+f"(acc[mt][nt][0]), "+f"(acc[mt][nt][1]),
                          "+f"(acc[mt][nt][2]), "+f"(acc[mt][nt][3])
                        : "r"(af[mt][0]), "r"(af[mt][1]), "r"(af[mt][2]), "r"(af[mt][3]),
                          "r"(bf[nt][0]), "r"(bf[nt][1]));
                }
        }
    }

    // epilogue: atomic-accumulate into out (token rows), weighted for experts
    int t4 = lane >> 2, t2 = lane & 3;
#pragma unroll
    for (int mt = 0; mt < 4; ++mt) {
#pragma unroll
        for (int h = 0; h < 2; ++h) {
            int r = row0 + wm * 64 + mt * 16 + h * 8 + t4;
            if (r < n) {
                int tok;
                float wt;
                if (g < NE) { tok = g_etok[g * TOK + r]; wt = g_ewt[g * TOK + r]; }
                else        { tok = r; wt = 1.f; }
                float* dst = out + (size_t)tok * DIM + col0 + wn * 32 + t2 * 2;
#pragma unroll
                for (int nt = 0; nt < 4; ++nt) {
                    atomicAdd(dst + nt * 8,     acc[mt][nt][2 * h] * wt);
                    atomicAdd(dst + nt * 8 + 1, acc[mt][nt][2 * h + 1] * wt);
                }
            }
        }
    }
}

// ---------------- launch ----------------
extern "C" void kernel_launch(void* const* d_in, const int* in_sizes, int n_in,
                              void* d_out, int out_size) {
    const float* feat = (const float*)d_in[0];
    const float* rw   = (const float*)d_in[1];
    const float* sw   = (const float*)d_in[2];
    const float* ew   = (const float*)d_in[3];
    float* out = (float*)d_out;

    cudaFuncSetAttribute(k_gemm, cudaFuncAttributeMaxDynamicSharedMemorySize, SMEM_SZ);

    k_zero<<<(out_size + 255) / 256, 256>>>(out, out_size);
    k_wsum<<<(DIM * DIM / 4) / 256, 256>>>(sw);
    k_ewh<<<(NE * DIM * DIM / 4) / 256, 256>>>(ew);
    k_router<<<TOK / 8, 256>>>(feat, rw);
    k_offaux<<<1, 1>>>(out + (out_size - 1));
    k_gemm<<<dim3(DIM / 128, TOK / 128, NE + 1), 256, SMEM_SZ>>>(out);
}

// round 6
// speedup vs baseline: 5.5355x; 1.0763x over previous
#include <cuda_runtime.h>
#include <cuda_fp16.h>
#include <math.h>
#include <stdint.h>

#define TOK 8192
#define DIM 1024
#define NE  16

// ---------------- device scratch (static, allocation-free) ----------------
__device__ __align__(1024) __half g_wsh[DIM * DIM];         // folded shared weight fp16 (2 MB)
__device__ __align__(1024) __half g_xh[TOK * DIM];          // fp16 feat (16 MB)
__device__ __align__(1024) __half g_ewh[NE * DIM * DIM];    // fp16 expert weights (32 MB)
__device__ int   g_ecount[NE];
__device__ float g_pi[NE];
__device__ int   g_cnt[NE];
__device__ int   g_etok[NE * TOK];
__device__ float g_ewt[NE * TOK];

__device__ __forceinline__ uint32_t smem_u32(const void* p) {
    uint32_t a;
    asm("{ .reg .u64 t; cvta.to.shared.u64 t, %1; cvt.u32.u64 %0, t; }" : "=r"(a) : "l"(p));
    return a;
}

#define CP16Z(dst, src, sz) \
    asm volatile("cp.async.cg.shared.global [%0], [%1], 16, %2;" \
        :: "r"(dst), "l"(src), "r"(sz) : "memory")
#define CP_COMMIT() asm volatile("cp.async.commit_group;" ::: "memory")
#define CP_WAIT1()  asm volatile("cp.async.wait_group 1;" ::: "memory")

// ---------------- prep: expert weights + folded shared weight -> fp16, reset ------
#define EW4BLKS ((NE * DIM * DIM / 4) / 256)
__global__ void k_prep(const float* __restrict__ sw, const float* __restrict__ ew) {
    int bid = blockIdx.x, tid = threadIdx.x;
    if (bid == 0 && tid < NE) { g_ecount[tid] = 0; g_pi[tid] = 0.f; g_cnt[tid] = 0; }
    if (bid < EW4BLKS) {
        int i = bid * 256 + tid;
        float4 v = ((const float4*)ew)[i];
        ((__half2*)g_ewh)[2 * i] = __floats2half2_rn(v.x, v.y);
        ((__half2*)g_ewh)[2 * i + 1] = __floats2half2_rn(v.z, v.w);
    } else {
        int i = (bid - EW4BLKS) * 256 + tid;
        const float4* s4 = (const float4*)sw;
        float4 a = s4[i];
        float4 b = s4[i + (DIM * DIM) / 4];
        ((__half2*)g_wsh)[2 * i] = __floats2half2_rn(a.x + b.x, a.y + b.y);
        ((__half2*)g_wsh)[2 * i + 1] = __floats2half2_rn(a.z + b.z, a.w + b.w);
    }
}

// ---------------- router: 512 threads, float2 smem, half2 feat copy ----------------
__global__ void __launch_bounds__(512) k_router(const float* __restrict__ x,
                                                const float* __restrict__ rw) {
    __shared__ float srw[NE * DIM];
    __shared__ float s_pi[NE];
    __shared__ int   s_cnt[NE];
    int tid = threadIdx.x;
    if (tid < NE) { s_pi[tid] = 0.f; s_cnt[tid] = 0; }
    for (int i = tid; i < NE * DIM; i += 512) srw[i] = rw[i];
    __syncthreads();

    int warp = tid >> 5, lane = tid & 31;
    int t = blockIdx.x * 16 + warp;
    const float2* xr = (const float2*)(x + (size_t)t * DIM);

    float2 xv[16];
#pragma unroll
    for (int j = 0; j < 16; ++j) xv[j] = xr[lane + 32 * j];

    // packed fp16 copy of feat
    __half2* xo = (__half2*)g_xh + (size_t)t * (DIM / 2);
#pragma unroll
    for (int j = 0; j < 16; ++j)
        xo[lane + 32 * j] = __floats2half2_rn(xv[j].x, xv[j].y);

    float logit[NE];
#pragma unroll
    for (int e = 0; e < NE; ++e) {
        const float2* w = (const float2*)(srw + e * DIM);
        float s = 0.f;
#pragma unroll
        for (int j = 0; j < 16; ++j) {
            float2 wv = w[lane + 32 * j];
            s += xv[j].x * wv.x + xv[j].y * wv.y;
        }
#pragma unroll
        for (int o = 16; o > 0; o >>= 1) s += __shfl_xor_sync(0xffffffffu, s, o);
        logit[e] = s;
    }

    int e1 = 0; float v1 = logit[0];
#pragma unroll
    for (int e = 1; e < NE; ++e) if (logit[e] > v1) { v1 = logit[e]; e1 = e; }
    int e2 = -1; float v2 = -3.4e38f;
#pragma unroll
    for (int e = 0; e < NE; ++e) if (e != e1 && logit[e] > v2) { v2 = logit[e]; e2 = e; }

    float w1 = 1.f / (1.f + expf(v2 - v1));
    float w2 = 1.f - w1;

    float se = 0.f;
#pragma unroll
    for (int e = 0; e < NE; ++e) se += expf(logit[e] - v1);
    float inv_se = 1.f / se;

    if (lane == 0) {
        atomicAdd(&s_cnt[e1], 1);
        atomicAdd(&s_cnt[e2], 1);
        int p1 = atomicAdd(&g_ecount[e1], 1);
        int p2 = atomicAdd(&g_ecount[e2], 1);
        g_etok[e1 * TOK + p1] = t;  g_ewt[e1 * TOK + p1] = w1;
        g_etok[e2 * TOK + p2] = t;  g_ewt[e2 * TOK + p2] = w2;
#pragma unroll
        for (int e = 0; e < NE; ++e)
            atomicAdd(&s_pi[e], expf(logit[e] - v1) * inv_se);
    }
    __syncthreads();
    if (tid < NE) {
        atomicAdd(&g_pi[tid], s_pi[tid]);
        atomicAdd(&g_cnt[tid], s_cnt[tid]);
    }
}

__global__ void k_offaux(float* __restrict__ aux_dst) {
    float a = 0.f;
    for (int e = 0; e < NE; ++e)
        a += (g_pi[e] / (float)TOK) * ((float)g_cnt[e] / (float)TOK);
    *aux_dst = a;
}

// ---------------- fp16 mma.sync GEMM (templated epilogue) ----------------
#define RSTRB   144
#define A_BYTES (128 * RSTRB)
#define STG_B   (2 * A_BYTES)
#define NSTG    3
#define SMEM_SZ (NSTG * STG_B)
#define NK      (DIM / 64)

template <bool SHARED>
__global__ void __launch_bounds__(256, 2) k_gemm(float* __restrict__ out) {
    int g = SHARED ? NE : blockIdx.z;
    int n = SHARED ? TOK : g_ecount[g];
    int row0 = blockIdx.y * 128;
    if (row0 >= n) return;
    int col0 = blockIdx.x * 128;

    const __half* Bbase = SHARED ? (g_wsh + (size_t)col0 * DIM)
                                 : (g_ewh + (size_t)g * DIM * DIM + (size_t)col0 * DIM);

    extern __shared__ __align__(1024) char smem[];
    uint32_t sb = smem_u32(smem);
    int tid = threadIdx.x;
    int wid = tid >> 5, lane = tid & 31;
    int wm = wid & 1, wn = wid >> 1;

    int ldrow = tid >> 3;
    int ldch = (tid & 7) * 16;

    int tk[4];
    uint32_t sz[4];
#pragma unroll
    for (int i = 0; i < 4; ++i) {
        int r = row0 + ldrow + i * 32;
        if (SHARED) { tk[i] = r; sz[i] = 16u; }
        else {
            bool v = (r < n);
            tk[i] = v ? g_etok[g * TOK + r] : 0;
            sz[i] = v ? 16u : 0u;
        }
    }

    int rA = lane & 15, cAb = lane >> 4;
    uint32_t aA0 = (uint32_t)(((wm * 64 + rA) * RSTRB) + cAb * 16);
    int rB = (lane & 7) + ((lane >> 4) << 3), cBb = (lane >> 3) & 1;
    uint32_t aB0 = (uint32_t)A_BYTES + (uint32_t)(((wn * 32 + rB) * RSTRB) + cBb * 16);

    float acc[4][4][4];
#pragma unroll
    for (int i = 0; i < 4; ++i)
#pragma unroll
        for (int j = 0; j < 4; ++j)
#pragma unroll
            for (int k = 0; k < 4; ++k) acc[i][j][k] = 0.f;

#pragma unroll
    for (int st = 0; st < 2; ++st) {
        uint32_t so = sb + (uint32_t)(st * STG_B);
        int kb = st * 128;
#pragma unroll
        for (int i = 0; i < 4; ++i) {
            int r = ldrow + i * 32;
            CP16Z(so + (uint32_t)(r * RSTRB + ldch),
                  (const char*)g_xh + (size_t)tk[i] * 2048 + kb + ldch, sz[i]);
            CP16Z(so + (uint32_t)A_BYTES + (uint32_t)(r * RSTRB + ldch),
                  (const char*)Bbase + (size_t)r * 2048 + kb + ldch, 16u);
        }
        CP_COMMIT();
    }

    for (int ks = 0; ks < NK; ++ks) {
        CP_WAIT1();
        __syncthreads();

        if (ks + 2 < NK) {
            uint32_t so = sb + (uint32_t)(((ks + 2) % NSTG) * STG_B);
            int kb = (ks + 2) * 128;
#pragma unroll
            for (int i = 0; i < 4; ++i) {
                int r = ldrow + i * 32;
                CP16Z(so + (uint32_t)(r * RSTRB + ldch),
                      (const char*)g_xh + (size_t)tk[i] * 2048 + kb + ldch, sz[i]);
                CP16Z(so + (uint32_t)A_BYTES + (uint32_t)(r * RSTRB + ldch),
                      (const char*)Bbase + (size_t)r * 2048 + kb + ldch, 16u);
            }
        }
        CP_COMMIT();

        uint32_t stg = sb + (uint32_t)((ks % NSTG) * STG_B);
#pragma unroll
        for (int sub = 0; sub < 4; ++sub) {
            uint32_t af[4][4];
            uint32_t bf[4][2];
#pragma unroll
            for (int mt = 0; mt < 4; ++mt) {
                uint32_t addr = stg + aA0 + (uint32_t)(mt * 16 * RSTRB + sub * 32);
                asm volatile("ldmatrix.sync.aligned.m8n8.x4.shared.b16 {%0,%1,%2,%3}, [%4];"
                    : "=r"(af[mt][0]), "=r"(af[mt][1]), "=r"(af[mt][2]), "=r"(af[mt][3])
                    : "r"(addr));
            }
#pragma unroll
            for (int p = 0; p < 2; ++p) {
                uint32_t addr = stg + aB0 + (uint32_t)(p * 16 * RSTRB + sub * 32);
                asm volatile("ldmatrix.sync.aligned.m8n8.x4.shared.b16 {%0,%1,%2,%3}, [%4];"
                    : "=r"(bf[2 * p][0]), "=r"(bf[2 * p][1]),
                      "=r"(bf[2 * p + 1][0]), "=r"(bf[2 * p + 1][1])
                    : "r"(addr));
            }
#pragma unroll
            for (int mt = 0; mt < 4; ++mt)
#pragma unroll
                for (int nt = 0; nt < 4; ++nt) {
                    asm volatile(
                        "mma.sync.aligned.m16n8k16.row.col.f32.f16.f16.f32 "
                        "{%0,%1,%2,%3}, {%4,%5,%6,%7}, {%8,%9}, {%0,%1,%2,%3};"
                        : "+f"(acc[mt][nt][0]), "+f"(acc[mt][nt][1]),
                          "+f"(acc[mt][nt][2]), "+f"(acc[mt][nt][3])
                        : "r"(af[mt][0]), "r"(af[mt][1]), "r"(af[mt][2]), "r"(af[mt][3]),
                          "r"(bf[nt][0]), "r"(bf[nt][1]));
                }
        }
    }

    int t4 = lane >> 2, t2 = lane & 3;
#pragma unroll
    for (int mt = 0; mt < 4; ++mt) {
#pragma unroll
        for (int h = 0; h < 2; ++h) {
            int r = row0 + wm * 64 + mt * 16 + h * 8 + t4;
            if (SHARED) {
                float* dst = out + (size_t)r * DIM + col0 + wn * 32 + t2 * 2;
#pragma unroll
                for (int nt = 0; nt < 4; ++nt)
                    *(float2*)(dst + nt * 8) =
                        make_float2(acc[mt][nt][2 * h], acc[mt][nt][2 * h + 1]);
            } else if (r < n) {
                int tok = g_etok[g * TOK + r];
                float wt = g_ewt[g * TOK + r];
                float* dst = out + (size_t)tok * DIM + col0 + wn * 32 + t2 * 2;
#pragma unroll
                for (int nt = 0; nt < 4; ++nt) {
                    atomicAdd(dst + nt * 8,     acc[mt][nt][2 * h] * wt);
                    atomicAdd(dst + nt * 8 + 1, acc[mt][nt][2 * h + 1] * wt);
                }
            }
        }
    }
}

// ---------------- launch ----------------
extern "C" void kernel_launch(void* const* d_in, const int* in_sizes, int n_in,
                              void* d_out, int out_size) {
    const float* feat = (const float*)d_in[0];
    const float* rw   = (const float*)d_in[1];
    const float* sw   = (const float*)d_in[2];
    const float* ew   = (const float*)d_in[3];
    float* out = (float*)d_out;

    cudaFuncSetAttribute(k_gemm<true>, cudaFuncAttributeMaxDynamicSharedMemorySize, SMEM_SZ);
    cudaFuncSetAttribute(k_gemm<false>, cudaFuncAttributeMaxDynamicSharedMemorySize, SMEM_SZ);

    k_prep<<<EW4BLKS + (DIM * DIM / 4) / 256, 256>>>(sw, ew);
    k_router<<<TOK / 16, 512>>>(feat, rw);
    k_offaux<<<1, 1>>>(out + (out_size - 1));
    k_gemm<true><<<dim3(DIM / 128, TOK / 128, 1), 256, SMEM_SZ>>>(out);
    k_gemm<false><<<dim3(DIM / 128, TOK / 128, NE), 256, SMEM_SZ>>>(out);
}

// round 7
// speedup vs baseline: 5.9686x; 1.0782x over previous
#include <cuda_runtime.h>
#include <cuda_fp16.h>
#include <math.h>
#include <stdint.h>

#define TOK 8192
#define DIM 1024
#define NE  16

// ---------------- device scratch (static, allocation-free) ----------------
__device__ __align__(1024) __half g_wsh[DIM * DIM];         // folded shared weight fp16 (2 MB)
__device__ __align__(1024) __half g_xh[TOK * DIM];          // fp16 feat (16 MB)
__device__ __align__(1024) __half g_ewh[NE * DIM * DIM];    // fp16 expert weights (32 MB)
__device__ int   g_ecount[NE];
__device__ float g_pi[NE];
__device__ int   g_cnt[NE];
__device__ int   g_etok[NE * TOK];
__device__ float g_ewt[NE * TOK];

__device__ __forceinline__ uint32_t smem_u32(const void* p) {
    uint32_t a;
    asm("{ .reg .u64 t; cvta.to.shared.u64 t, %1; cvt.u32.u64 %0, t; }" : "=r"(a) : "l"(p));
    return a;
}

#define CP16(dst, src) \
    asm volatile("cp.async.cg.shared.global [%0], [%1], 16;" :: "r"(dst), "l"(src) : "memory")
#define CP_COMMIT() asm volatile("cp.async.commit_group;" ::: "memory")
#define CP_WAIT1()  asm volatile("cp.async.wait_group 1;" ::: "memory")

// ---------------- prep: expert weights + folded shared weight -> fp16, reset ------
#define EW4BLKS ((NE * DIM * DIM / 4) / 256)
__global__ void k_prep(const float* __restrict__ sw, const float* __restrict__ ew) {
    int bid = blockIdx.x, tid = threadIdx.x;
    if (bid == 0 && tid < NE) { g_ecount[tid] = 0; g_pi[tid] = 0.f; g_cnt[tid] = 0; }
    if (bid < EW4BLKS) {
        int i = bid * 256 + tid;
        float4 v = ((const float4*)ew)[i];
        ((__half2*)g_ewh)[2 * i] = __floats2half2_rn(v.x, v.y);
        ((__half2*)g_ewh)[2 * i + 1] = __floats2half2_rn(v.z, v.w);
    } else {
        int i = (bid - EW4BLKS) * 256 + tid;
        const float4* s4 = (const float4*)sw;
        float4 a = s4[i];
        float4 b = s4[i + (DIM * DIM) / 4];
        ((__half2*)g_wsh)[2 * i] = __floats2half2_rn(a.x + b.x, a.y + b.y);
        ((__half2*)g_wsh)[2 * i + 1] = __floats2half2_rn(a.z + b.z, a.w + b.w);
    }
}

// ---------------- router ----------------
__global__ void __launch_bounds__(512) k_router(const float* __restrict__ x,
                                                const float* __restrict__ rw) {
    __shared__ float srw[NE * DIM];
    __shared__ float s_pi[NE];
    __shared__ int   s_cnt[NE];
    int tid = threadIdx.x;
    if (tid < NE) { s_pi[tid] = 0.f; s_cnt[tid] = 0; }
    for (int i = tid; i < NE * DIM; i += 512) srw[i] = rw[i];
    __syncthreads();

    int warp = tid >> 5, lane = tid & 31;
    int t = blockIdx.x * 16 + warp;
    const float2* xr = (const float2*)(x + (size_t)t * DIM);

    float2 xv[16];
#pragma unroll
    for (int j = 0; j < 16; ++j) xv[j] = xr[lane + 32 * j];

    __half2* xo = (__half2*)g_xh + (size_t)t * (DIM / 2);
#pragma unroll
    for (int j = 0; j < 16; ++j)
        xo[lane + 32 * j] = __floats2half2_rn(xv[j].x, xv[j].y);

    float logit[NE];
#pragma unroll
    for (int e = 0; e < NE; ++e) {
        const float2* w = (const float2*)(srw + e * DIM);
        float s = 0.f;
#pragma unroll
        for (int j = 0; j < 16; ++j) {
            float2 wv = w[lane + 32 * j];
            s += xv[j].x * wv.x + xv[j].y * wv.y;
        }
#pragma unroll
        for (int o = 16; o > 0; o >>= 1) s += __shfl_xor_sync(0xffffffffu, s, o);
        logit[e] = s;
    }

    int e1 = 0; float v1 = logit[0];
#pragma unroll
    for (int e = 1; e < NE; ++e) if (logit[e] > v1) { v1 = logit[e]; e1 = e; }
    int e2 = -1; float v2 = -3.4e38f;
#pragma unroll
    for (int e = 0; e < NE; ++e) if (e != e1 && logit[e] > v2) { v2 = logit[e]; e2 = e; }

    float w1 = 1.f / (1.f + expf(v2 - v1));
    float w2 = 1.f - w1;

    float se = 0.f;
#pragma unroll
    for (int e = 0; e < NE; ++e) se += expf(logit[e] - v1);
    float inv_se = 1.f / se;

    if (lane == 0) {
        atomicAdd(&s_cnt[e1], 1);
        atomicAdd(&s_cnt[e2], 1);
        int p1 = atomicAdd(&g_ecount[e1], 1);
        int p2 = atomicAdd(&g_ecount[e2], 1);
        g_etok[e1 * TOK + p1] = t;  g_ewt[e1 * TOK + p1] = w1;
        g_etok[e2 * TOK + p2] = t;  g_ewt[e2 * TOK + p2] = w2;
#pragma unroll
        for (int e = 0; e < NE; ++e)
            atomicAdd(&s_pi[e], expf(logit[e] - v1) * inv_se);
    }
    __syncthreads();
    if (tid < NE) {
        atomicAdd(&g_pi[tid], s_pi[tid]);
        atomicAdd(&g_cnt[tid], s_cnt[tid]);
    }
}

// ---------------- fp16 mma.sync GEMM, software-pipelined fragments ----------------
#define RSTRB   144
#define A_BYTES (128 * RSTRB)
#define STG_B   (2 * A_BYTES)
#define NSTG    3
#define SMEM_SZ (NSTG * STG_B)
#define NK      (DIM / 64)

#define LD_FRAGS(buf, stgbase, sub)                                                   \
    do {                                                                              \
        uint32_t _sg = (stgbase);                                                     \
        _Pragma("unroll")                                                             \
        for (int mt = 0; mt < 4; ++mt) {                                              \
            uint32_t addr = _sg + aA0 + (uint32_t)(mt * 16 * RSTRB + (sub) * 32);     \
            asm volatile("ldmatrix.sync.aligned.m8n8.x4.shared.b16 {%0,%1,%2,%3}, [%4];" \
                : "=r"(af[buf][mt][0]), "=r"(af[buf][mt][1]),                         \
                  "=r"(af[buf][mt][2]), "=r"(af[buf][mt][3])                          \
                : "r"(addr));                                                         \
        }                                                                             \
        _Pragma("unroll")                                                             \
        for (int p = 0; p < 2; ++p) {                                                 \
            uint32_t addr = _sg + aB0 + (uint32_t)(p * 16 * RSTRB + (sub) * 32);      \
            asm volatile("ldmatrix.sync.aligned.m8n8.x4.shared.b16 {%0,%1,%2,%3}, [%4];" \
                : "=r"(bf[buf][2 * p][0]), "=r"(bf[buf][2 * p][1]),                   \
                  "=r"(bf[buf][2 * p + 1][0]), "=r"(bf[buf][2 * p + 1][1])            \
                : "r"(addr));                                                         \
        }                                                                             \
    } while (0)

#define DO_MMAS(buf)                                                                  \
    do {                                                                              \
        _Pragma("unroll")                                                             \
        for (int mt = 0; mt < 4; ++mt)                                                \
            _Pragma("unroll")                                                         \
            for (int nt = 0; nt < 4; ++nt) {                                          \
                asm volatile(                                                         \
                    "mma.sync.aligned.m16n8k16.row.col.f32.f16.f16.f32 "              \
                    "{%0,%1,%2,%3}, {%4,%5,%6,%7}, {%8,%9}, {%0,%1,%2,%3};"           \
                    : "+f"(acc[mt][nt][0]), "+f"(acc[mt][nt][1]),                     \
                      "+f"(acc[mt][nt][2]), "+f"(acc[mt][nt][3])                      \
                    : "r"(af[buf][mt][0]), "r"(af[buf][mt][1]),                       \
                      "r"(af[buf][mt][2]), "r"(af[buf][mt][3]),                       \
                      "r"(bf[buf][nt][0]), "r"(bf[buf][nt][1]));                      \
            }                                                                         \
    } while (0)

#define ISSUE_STAGE(stgbuf, kb)                                                       \
    do {                                                                              \
        uint32_t so = sb + (uint32_t)((stgbuf) * STG_B);                              \
        _Pragma("unroll")                                                             \
        for (int i = 0; i < 4; ++i) {                                                 \
            CP16(so + dA0 + (uint32_t)(i * 32 * RSTRB), Ap[i] + (kb));                \
            CP16(so + (uint32_t)A_BYTES + dA0 + (uint32_t)(i * 32 * RSTRB),           \
                 Bp + (size_t)i * 65536 + (kb));                                      \
        }                                                                             \
    } while (0)

template <bool SHARED>
__global__ void __launch_bounds__(256, 2) k_gemm(float* __restrict__ out,
                                                 float* __restrict__ aux_dst) {
    int g = SHARED ? NE : blockIdx.z;
    int n = SHARED ? TOK : g_ecount[g];
    int row0 = blockIdx.y * 128;
    int tid = threadIdx.x;

    if (SHARED && blockIdx.x == 0 && blockIdx.y == 0 && tid == 0) {
        float a = 0.f;
#pragma unroll
        for (int e = 0; e < NE; ++e)
            a += (g_pi[e] / (float)TOK) * ((float)g_cnt[e] / (float)TOK);
        *aux_dst = a;
    }
    if (row0 >= n) return;
    int col0 = blockIdx.x * 128;

    const __half* Bbase = SHARED ? (g_wsh + (size_t)col0 * DIM)
                                 : (g_ewh + (size_t)g * DIM * DIM + (size_t)col0 * DIM);

    extern __shared__ __align__(1024) char smem[];
    uint32_t sb = smem_u32(smem);
    int wid = tid >> 5, lane = tid & 31;
    int wm = wid & 1, wn = wid >> 1;

    int ldrow = tid >> 3;
    int ldch = (tid & 7) * 16;
    uint32_t dA0 = (uint32_t)(ldrow * RSTRB + ldch);

    // A source pointers (gathered rows; ragged tail clamped to a valid token,
    // its results never stored)
    const char* Ap[4];
#pragma unroll
    for (int i = 0; i < 4; ++i) {
        int r = row0 + ldrow + i * 32;
        int rc = (r < n) ? r : (n - 1);
        int t = SHARED ? r : g_etok[g * TOK + rc];
        Ap[i] = (const char*)g_xh + (size_t)t * 2048 + ldch;
    }
    const char* Bp = (const char*)Bbase + (size_t)ldrow * 2048 + ldch;

    int rA = lane & 15, cAb = lane >> 4;
    uint32_t aA0 = (uint32_t)(((wm * 64 + rA) * RSTRB) + cAb * 16);
    int rB = (lane & 7) + ((lane >> 4) << 3), cBb = (lane >> 3) & 1;
    uint32_t aB0 = (uint32_t)A_BYTES + (uint32_t)(((wn * 32 + rB) * RSTRB) + cBb * 16);

    float acc[4][4][4];
#pragma unroll
    for (int i = 0; i < 4; ++i)
#pragma unroll
        for (int j = 0; j < 4; ++j)
#pragma unroll
            for (int k = 0; k < 4; ++k) acc[i][j][k] = 0.f;

    uint32_t af[2][4][4];
    uint32_t bf[2][4][2];

    // prologue: stages 0,1 in flight; frags(stage0, sub0) into buf0
    ISSUE_STAGE(0, 0);
    CP_COMMIT();
    ISSUE_STAGE(1, 128);
    CP_COMMIT();
    CP_WAIT1();
    __syncthreads();
    LD_FRAGS(0, sb, 0);

    for (int ks = 0; ks < NK; ++ks) {
        // overwrites buffer (ks-1)%3; sync at end of iter ks-1 covered all its reads
        if (ks + 2 < NK) ISSUE_STAGE((ks + 2) % NSTG, (ks + 2) * 128);
        CP_COMMIT();

        uint32_t stg = sb + (uint32_t)((ks % NSTG) * STG_B);
#pragma unroll
        for (int sub = 0; sub < 4; ++sub) {
            int cur = sub & 1, nxt = cur ^ 1;
            if (sub < 3) {
                LD_FRAGS(nxt, stg, sub + 1);
            } else if (ks + 1 < NK) {
                CP_WAIT1();
                __syncthreads();
                LD_FRAGS(nxt, sb + (uint32_t)(((ks + 1) % NSTG) * STG_B), 0);
            }
            DO_MMAS(cur);
        }
    }

    // epilogue
    int t4 = lane >> 2, t2 = lane & 3;
#pragma unroll
    for (int mt = 0; mt < 4; ++mt) {
#pragma unroll
        for (int h = 0; h < 2; ++h) {
            int r = row0 + wm * 64 + mt * 16 + h * 8 + t4;
            if (SHARED) {
                float* dst = out + (size_t)r * DIM + col0 + wn * 32 + t2 * 2;
#pragma unroll
                for (int nt = 0; nt < 4; ++nt)
                    *(float2*)(dst + nt * 8) =
                        make_float2(acc[mt][nt][2 * h], acc[mt][nt][2 * h + 1]);
            } else if (r < n) {
                int tok = g_etok[g * TOK + r];
                float wt = g_ewt[g * TOK + r];
                float* dst = out + (size_t)tok * DIM + col0 + wn * 32 + t2 * 2;
#pragma unroll
                for (int nt = 0; nt < 4; ++nt) {
                    atomicAdd(dst + nt * 8,     acc[mt][nt][2 * h] * wt);
                    atomicAdd(dst + nt * 8 + 1, acc[mt][nt][2 * h + 1] * wt);
                }
            }
        }
    }
}

// ---------------- launch ----------------
extern "C" void kernel_launch(void* const* d_in, const int* in_sizes, int n_in,
                              void* d_out, int out_size) {
    const float* feat = (const float*)d_in[0];
    const float* rw   = (const float*)d_in[1];
    const float* sw   = (const float*)d_in[2];
    const float* ew   = (const float*)d_in[3];
    float* out = (float*)d_out;
    float* aux = out + (out_size - 1);

    cudaFuncSetAttribute(k_gemm<true>, cudaFuncAttributeMaxDynamicSharedMemorySize, SMEM_SZ);
    cudaFuncSetAttribute(k_gemm<false>, cudaFuncAttributeMaxDynamicSharedMemorySize, SMEM_SZ);

    k_prep<<<EW4BLKS + (DIM * DIM / 4) / 256, 256>>>(sw, ew);
    k_router<<<TOK / 16, 512>>>(feat, rw);
    k_gemm<true><<<dim3(DIM / 128, TOK / 128, 1), 256, SMEM_SZ>>>(out, aux);
    k_gemm<false><<<dim3(DIM / 128, TOK / 128, NE), 256, SMEM_SZ>>>(out, aux);
}

// round 8
// speedup vs baseline: 6.1082x; 1.0234x over previous
#include <cuda_runtime.h>
#include <cuda_fp16.h>
#include <math.h>
#include <stdint.h>

#define TOK 8192
#define DIM 1024
#define NE  16

// ---------------- device scratch (static, allocation-free) ----------------
__device__ __align__(1024) __half g_wsh[DIM * DIM];         // folded shared weight fp16 (2 MB)
__device__ __align__(1024) __half g_xh[TOK * DIM];          // fp16 feat (16 MB)
__device__ __align__(1024) __half g_ewh[NE * DIM * DIM];    // fp16 expert weights (32 MB)
__device__ int   g_ecount[NE];
__device__ float g_pi[NE];
__device__ int   g_cnt[NE];
__device__ int   g_etok[NE * TOK];
__device__ float g_ewt[NE * TOK];

__device__ __forceinline__ uint32_t smem_u32(const void* p) {
    uint32_t a;
    asm("{ .reg .u64 t; cvta.to.shared.u64 t, %1; cvt.u32.u64 %0, t; }" : "=r"(a) : "l"(p));
    return a;
}

#define CP16(dst, src) \
    asm volatile("cp.async.cg.shared.global [%0], [%1], 16;" :: "r"(dst), "l"(src) : "memory")
#define CP_COMMIT() asm volatile("cp.async.commit_group;" ::: "memory")
#define CP_WAIT1()  asm volatile("cp.async.wait_group 1;" ::: "memory")

// ---------------- prep: expert weights + folded shared weight -> fp16, reset ------
#define EW4BLKS ((NE * DIM * DIM / 4) / 256)
__global__ void k_prep(const float* __restrict__ sw, const float* __restrict__ ew) {
    int bid = blockIdx.x, tid = threadIdx.x;
    if (bid == 0 && tid < NE) { g_ecount[tid] = 0; g_pi[tid] = 0.f; g_cnt[tid] = 0; }
    if (bid < EW4BLKS) {
        int i = bid * 256 + tid;
        float4 v = ((const float4*)ew)[i];
        ((__half2*)g_ewh)[2 * i] = __floats2half2_rn(v.x, v.y);
        ((__half2*)g_ewh)[2 * i + 1] = __floats2half2_rn(v.z, v.w);
    } else {
        int i = (bid - EW4BLKS) * 256 + tid;
        const float4* s4 = (const float4*)sw;
        float4 a = s4[i];
        float4 b = s4[i + (DIM * DIM) / 4];
        ((__half2*)g_wsh)[2 * i] = __floats2half2_rn(a.x + b.x, a.y + b.y);
        ((__half2*)g_wsh)[2 * i + 1] = __floats2half2_rn(a.z + b.z, a.w + b.w);
    }
}

// ---------------- router ----------------
__global__ void __launch_bounds__(512) k_router(const float* __restrict__ x,
                                                const float* __restrict__ rw) {
    __shared__ float srw[NE * DIM];
    __shared__ float s_pi[NE];
    __shared__ int   s_cnt[NE];
    int tid = threadIdx.x;
    if (tid < NE) { s_pi[tid] = 0.f; s_cnt[tid] = 0; }
    for (int i = tid; i < NE * DIM; i += 512) srw[i] = rw[i];
    __syncthreads();

    int warp = tid >> 5, lane = tid & 31;
    int t = blockIdx.x * 16 + warp;
    const float2* xr = (const float2*)(x + (size_t)t * DIM);

    float2 xv[16];
#pragma unroll
    for (int j = 0; j < 16; ++j) xv[j] = xr[lane + 32 * j];

    __half2* xo = (__half2*)g_xh + (size_t)t * (DIM / 2);
#pragma unroll
    for (int j = 0; j < 16; ++j)
        xo[lane + 32 * j] = __floats2half2_rn(xv[j].x, xv[j].y);

    float logit[NE];
#pragma unroll
    for (int e = 0; e < NE; ++e) {
        const float2* w = (const float2*)(srw + e * DIM);
        float s = 0.f;
#pragma unroll
        for (int j = 0; j < 16; ++j) {
            float2 wv = w[lane + 32 * j];
            s += xv[j].x * wv.x + xv[j].y * wv.y;
        }
#pragma unroll
        for (int o = 16; o > 0; o >>= 1) s += __shfl_xor_sync(0xffffffffu, s, o);
        logit[e] = s;
    }

    int e1 = 0; float v1 = logit[0];
#pragma unroll
    for (int e = 1; e < NE; ++e) if (logit[e] > v1) { v1 = logit[e]; e1 = e; }
    int e2 = -1; float v2 = -3.4e38f;
#pragma unroll
    for (int e = 0; e < NE; ++e) if (e != e1 && logit[e] > v2) { v2 = logit[e]; e2 = e; }

    float w1 = 1.f / (1.f + expf(v2 - v1));
    float w2 = 1.f - w1;

    float se = 0.f;
#pragma unroll
    for (int e = 0; e < NE; ++e) se += expf(logit[e] - v1);
    float inv_se = 1.f / se;

    if (lane == 0) {
        atomicAdd(&s_cnt[e1], 1);
        atomicAdd(&s_cnt[e2], 1);
        int p1 = atomicAdd(&g_ecount[e1], 1);
        int p2 = atomicAdd(&g_ecount[e2], 1);
        g_etok[e1 * TOK + p1] = t;  g_ewt[e1 * TOK + p1] = w1;
        g_etok[e2 * TOK + p2] = t;  g_ewt[e2 * TOK + p2] = w2;
#pragma unroll
        for (int e = 0; e < NE; ++e)
            atomicAdd(&s_pi[e], expf(logit[e] - v1) * inv_se);
    }
    __syncthreads();
    if (tid < NE) {
        atomicAdd(&g_pi[tid], s_pi[tid]);
        atomicAdd(&g_cnt[tid], s_cnt[tid]);
    }
}

// ---------------- fp16 mma.sync GEMM: 128 threads, warp tile 64x64 ----------------
#define RSTRB   144
#define A_BYTES (128 * RSTRB)
#define STG_B   (2 * A_BYTES)
#define NSTG    3
#define SMEM_SZ (NSTG * STG_B)
#define NK      (DIM / 64)

#define LD_FRAGS(buf, stgbase, sub)                                                   \
    do {                                                                              \
        uint32_t _sg = (stgbase);                                                     \
        _Pragma("unroll")                                                             \
        for (int mt = 0; mt < 4; ++mt) {                                              \
            uint32_t addr = _sg + aA0 + (uint32_t)(mt * 16 * RSTRB + (sub) * 32);     \
            asm volatile("ldmatrix.sync.aligned.m8n8.x4.shared.b16 {%0,%1,%2,%3}, [%4];" \
                : "=r"(af[buf][mt][0]), "=r"(af[buf][mt][1]),                         \
                  "=r"(af[buf][mt][2]), "=r"(af[buf][mt][3])                          \
                : "r"(addr));                                                         \
        }                                                                             \
        _Pragma("unroll")                                                             \
        for (int p = 0; p < 4; ++p) {                                                 \
            uint32_t addr = _sg + aB0 + (uint32_t)(p * 16 * RSTRB + (sub) * 32);      \
            asm volatile("ldmatrix.sync.aligned.m8n8.x4.shared.b16 {%0,%1,%2,%3}, [%4];" \
                : "=r"(bf[buf][2 * p][0]), "=r"(bf[buf][2 * p][1]),                   \
                  "=r"(bf[buf][2 * p + 1][0]), "=r"(bf[buf][2 * p + 1][1])            \
                : "r"(addr));                                                         \
        }                                                                             \
    } while (0)

#define DO_MMAS(buf)                                                                  \
    do {                                                                              \
        _Pragma("unroll")                                                             \
        for (int mt = 0; mt < 4; ++mt)                                                \
            _Pragma("unroll")                                                         \
            for (int nt = 0; nt < 8; ++nt) {                                          \
                asm volatile(                                                         \
                    "mma.sync.aligned.m16n8k16.row.col.f32.f16.f16.f32 "              \
                    "{%0,%1,%2,%3}, {%4,%5,%6,%7}, {%8,%9}, {%0,%1,%2,%3};"           \
                    : "+f"(acc[mt][nt][0]), "+f"(acc[mt][nt][1]),                     \
                      "+f"(acc[mt][nt][2]), "+f"(acc[mt][nt][3])                      \
                    : "r"(af[buf][mt][0]), "r"(af[buf][mt][1]),                       \
                      "r"(af[buf][mt][2]), "r"(af[buf][mt][3]),                       \
                      "r"(bf[buf][nt][0]), "r"(bf[buf][nt][1]));                      \
            }                                                                         \
    } while (0)

#define ISSUE_STAGE(stgbuf, kb)                                                       \
    do {                                                                              \
        uint32_t so = sb + (uint32_t)((stgbuf) * STG_B);                              \
        _Pragma("unroll")                                                             \
        for (int i = 0; i < 8; ++i) {                                                 \
            CP16(so + dA0 + (uint32_t)(i * 16 * RSTRB), Ap[i] + (kb));                \
            CP16(so + (uint32_t)A_BYTES + dA0 + (uint32_t)(i * 16 * RSTRB),           \
                 Bp + (size_t)i * 32768 + (kb));                                      \
        }                                                                             \
    } while (0)

template <bool SHARED>
__global__ void __launch_bounds__(128, 2) k_gemm(float* __restrict__ out,
                                                 float* __restrict__ aux_dst) {
    int g = SHARED ? NE : blockIdx.z;
    int n = SHARED ? TOK : g_ecount[g];
    int row0 = blockIdx.y * 128;
    int tid = threadIdx.x;

    if (SHARED && blockIdx.x == 0 && blockIdx.y == 0 && tid == 0) {
        float a = 0.f;
#pragma unroll
        for (int e = 0; e < NE; ++e)
            a += (g_pi[e] / (float)TOK) * ((float)g_cnt[e] / (float)TOK);
        *aux_dst = a;
    }
    if (row0 >= n) return;
    int col0 = blockIdx.x * 128;

    const __half* Bbase = SHARED ? (g_wsh + (size_t)col0 * DIM)
                                 : (g_ewh + (size_t)g * DIM * DIM + (size_t)col0 * DIM);

    extern __shared__ __align__(1024) char smem[];
    uint32_t sb = smem_u32(smem);
    int wid = tid >> 5, lane = tid & 31;
    int wm = wid & 1, wn = wid >> 1;       // 2x2 warp grid, warp tile 64x64

    int ldrow = tid >> 3;                  // 0..15
    int ldch = (tid & 7) * 16;
    uint32_t dA0 = (uint32_t)(ldrow * RSTRB + ldch);

    // A source pointers (8 rows per thread, gathered; ragged tail clamped)
    const char* Ap[8];
#pragma unroll
    for (int i = 0; i < 8; ++i) {
        int r = row0 + ldrow + i * 16;
        int rc = (r < n) ? r : (n - 1);
        int t = SHARED ? r : g_etok[g * TOK + rc];
        Ap[i] = (const char*)g_xh + (size_t)t * 2048 + ldch;
    }
    const char* Bp = (const char*)Bbase + (size_t)ldrow * 2048 + ldch;

    int rA = lane & 15, cAb = lane >> 4;
    uint32_t aA0 = (uint32_t)(((wm * 64 + rA) * RSTRB) + cAb * 16);
    int rB = (lane & 7) + ((lane >> 4) << 3), cBb = (lane >> 3) & 1;
    uint32_t aB0 = (uint32_t)A_BYTES + (uint32_t)(((wn * 64 + rB) * RSTRB) + cBb * 16);

    float acc[4][8][4];
#pragma unroll
    for (int i = 0; i < 4; ++i)
#pragma unroll
        for (int j = 0; j < 8; ++j)
#pragma unroll
            for (int k = 0; k < 4; ++k) acc[i][j][k] = 0.f;

    uint32_t af[2][4][4];
    uint32_t bf[2][8][2];

    // prologue
    ISSUE_STAGE(0, 0);
    CP_COMMIT();
    ISSUE_STAGE(1, 128);
    CP_COMMIT();
    CP_WAIT1();
    __syncthreads();
    LD_FRAGS(0, sb, 0);

    for (int ks = 0; ks < NK; ++ks) {
        if (ks + 2 < NK) ISSUE_STAGE((ks + 2) % NSTG, (ks + 2) * 128);
        CP_COMMIT();

        uint32_t stg = sb + (uint32_t)((ks % NSTG) * STG_B);
#pragma unroll
        for (int sub = 0; sub < 4; ++sub) {
            int cur = sub & 1, nxt = cur ^ 1;
            if (sub < 3) {
                LD_FRAGS(nxt, stg, sub + 1);
            } else if (ks + 1 < NK) {
                CP_WAIT1();
                __syncthreads();
                LD_FRAGS(nxt, sb + (uint32_t)(((ks + 1) % NSTG) * STG_B), 0);
            }
            DO_MMAS(cur);
        }
    }

    // epilogue
    int t4 = lane >> 2, t2 = lane & 3;
#pragma unroll
    for (int mt = 0; mt < 4; ++mt) {
#pragma unroll
        for (int h = 0; h < 2; ++h) {
            int r = row0 + wm * 64 + mt * 16 + h * 8 + t4;
            if (SHARED) {
                float* dst = out + (size_t)r * DIM + col0 + wn * 64 + t2 * 2;
#pragma unroll
                for (int nt = 0; nt < 8; ++nt)
                    *(float2*)(dst + nt * 8) =
                        make_float2(acc[mt][nt][2 * h], acc[mt][nt][2 * h + 1]);
            } else if (r < n) {
                int tok = g_etok[g * TOK + r];
                float wt = g_ewt[g * TOK + r];
                float* dst = out + (size_t)tok * DIM + col0 + wn * 64 + t2 * 2;
#pragma unroll
                for (int nt = 0; nt < 8; ++nt) {
                    atomicAdd(dst + nt * 8,     acc[mt][nt][2 * h] * wt);
                    atomicAdd(dst + nt * 8 + 1, acc[mt][nt][2 * h + 1] * wt);
                }
            }
        }
    }
}

// ---------------- launch ----------------
extern "C" void kernel_launch(void* const* d_in, const int* in_sizes, int n_in,
                              void* d_out, int out_size) {
    const float* feat = (const float*)d_in[0];
    const float* rw   = (const float*)d_in[1];
    const float* sw   = (const float*)d_in[2];
    const float* ew   = (const float*)d_in[3];
    float* out = (float*)d_out;
    float* aux = out + (out_size - 1);

    cudaFuncSetAttribute(k_gemm<true>, cudaFuncAttributeMaxDynamicSharedMemorySize, SMEM_SZ);
    cudaFuncSetAttribute(k_gemm<false>, cudaFuncAttributeMaxDynamicSharedMemorySize, SMEM_SZ);

    k_prep<<<EW4BLKS + (DIM * DIM / 4) / 256, 256>>>(sw, ew);
    k_router<<<TOK / 16, 512>>>(feat, rw);
    k_gemm<true><<<dim3(DIM / 128, TOK / 128, 1), 128, SMEM_SZ>>>(out, aux);
    k_gemm<false><<<dim3(DIM / 128, TOK / 128, NE), 128, SMEM_SZ>>>(out, aux);
}